// round 7
// baseline (speedup 1.0000x reference)
#include <cuda_runtime.h>
#include <cuda_fp16.h>
#include <cstdint>
#include <cstddef>

// ---------------------------------------------------------------------------
// Problem constants (MambaVisionMixer, B=4, L=2048)
// ---------------------------------------------------------------------------
#define B_SZ    4
#define LSEQ    2048
#define DMODEL  1024
#define DINNER  2048
#define DHALF   1024
#define DSTATE  16
#define DTRANK  64
#define XDBL_N  96
#define MROWS   (B_SZ*LSEQ)   // 8192
#define NCHUNK  16
#define LCHUNK  (LSEQ/NCHUNK) // 128

typedef __half h16;

// ---------------------------------------------------------------------------
// Device scratch (static __device__ arrays — no allocations)
// ---------------------------------------------------------------------------
__device__ float g_xz   [(size_t)MROWS * DINNER];   // 64 MB
__device__ float g_xdbl [(size_t)MROWS * XDBL_N];   // 3 MB
__device__ float g_delta[(size_t)MROWS * DHALF];    // 32 MB

__device__ float g_q [(size_t)B_SZ * NCHUNK * DSTATE * DHALF];  // 4 MB
__device__ float g_hs[(size_t)B_SZ * NCHUNK * DSTATE * DHALF];  // 4 MB
__device__ float g_S [(size_t)B_SZ * NCHUNK * DHALF];           // 256 KB

__device__ h16 g_a1h[(size_t)MROWS * DMODEL];      // x hi
__device__ h16 g_a1l[(size_t)MROWS * DMODEL];      // x lo
__device__ h16 g_b1h[(size_t)DINNER * DMODEL];     // W_in^T hi  [2048,1024]
__device__ h16 g_xsh[(size_t)MROWS * DHALF];       // xs hi
__device__ h16 g_xsl[(size_t)MROWS * DHALF];       // xs lo
__device__ h16 g_bxh[(size_t)XDBL_N * DHALF];      // W_xdbl^T [96,1024]
__device__ h16 g_bxl[(size_t)XDBL_N * DHALF];
__device__ h16 g_dth[(size_t)MROWS * DTRANK];      // dt_low hi [8192,64]
__device__ h16 g_dtl[(size_t)MROWS * DTRANK];
__device__ h16 g_bdh[(size_t)DHALF * DTRANK];      // W_dt^T [1024,64]
__device__ h16 g_bdl[(size_t)DHALF * DTRANK];
__device__ h16 g_ch [(size_t)MROWS * DINNER];      // [y|z] hi [8192,2048]
__device__ h16 g_cl [(size_t)MROWS * DINNER];
__device__ h16 g_b2h[(size_t)DMODEL * DINNER];     // W_out^T [1024,2048]

// ---------------------------------------------------------------------------
// Helpers (sm_80-era ISA only: compiles at compute_103 non-'a' target)
// ---------------------------------------------------------------------------
__device__ __forceinline__ uint32_t smem_u32(const void* p) {
    uint32_t r;
    asm("{ .reg .u64 t; cvta.to.shared.u64 t, %1; cvt.u32.u64 %0, t; }"
        : "=r"(r) : "l"(p));
    return r;
}

#define CP16(dst, src) \
    asm volatile("cp.async.cg.shared.global [%0], [%1], 16;" \
        :: "r"(dst), "l"(src) : "memory")
#define CP16Z(dst, src, sz) \
    asm volatile("cp.async.cg.shared.global [%0], [%1], 16, %2;" \
        :: "r"(dst), "l"(src), "r"(sz) : "memory")
#define CP_COMMIT() asm volatile("cp.async.commit_group;" ::: "memory")
#define CP_WAIT1()  asm volatile("cp.async.wait_group 1;" ::: "memory")

__device__ __forceinline__ void ldsm4(uint32_t* r, uint32_t addr) {
    asm volatile("ldmatrix.sync.aligned.m8n8.x4.shared.b16 {%0,%1,%2,%3}, [%4];"
        : "=r"(r[0]), "=r"(r[1]), "=r"(r[2]), "=r"(r[3]) : "r"(addr));
}

__device__ __forceinline__ void mma16816(float* d, const uint32_t* a,
                                         const uint32_t* b) {
    asm volatile(
        "mma.sync.aligned.m16n8k16.row.col.f32.f16.f16.f32 "
        "{%0,%1,%2,%3}, {%4,%5,%6,%7}, {%8,%9}, {%0,%1,%2,%3};"
        : "+f"(d[0]), "+f"(d[1]), "+f"(d[2]), "+f"(d[3])
        : "r"(a[0]), "r"(a[1]), "r"(a[2]), "r"(a[3]), "r"(b[0]), "r"(b[1]));
}

__device__ __forceinline__ float softplus_f(float x) {
    return fmaxf(x, 0.0f) + log1pf(expf(-fabsf(x)));
}
__device__ __forceinline__ float silu_f(float x) {
    return x / (1.0f + expf(-x));
}
__device__ __forceinline__ void split_h16(float v, h16& h, h16& l) {
    h = __float2half_rn(v);
    l = __float2half_rn(v - __half2float(h));
}

// ---------------------------------------------------------------------------
// Tensor-core GEMM (mma.sync fp16, fp32 accum) with fp16-split emulation.
//   C[M,N] = A[M,K] @ B^T   (B stored [N,K] row-major)
//   NSTREAM==2: streams (Ahi,Bhi), (Alo,Bhi)   -> error ~ A*Blo ~ 2^-12
//   NSTREAM==3: streams (Ahi,Bhi), (Ahi,Blo), (Alo,Bhi) -> error ~ 2^-22
//   CTA BMx128, 8 warps (2x4), warp tile (BM/2)x32.
//   BK=64: stage = BM*128B (A) + 128*128B (B); 3 buffers, 2 chunks in flight,
//   ONE __syncthreads per chunk (top barrier protects the slot overwritten by
//   the load issued this iteration: it was last read in iteration i-1).
//   Smem rows 128B; SW128 swizzle chunk c ^= row&7 -> conflict-free ldmatrix.
//   DTSPLIT: additionally write fp16 hi/lo of cols [0,64) to dth/dtl.
// ---------------------------------------------------------------------------
template <int BM, int NSTREAM, bool SOFTPLUS, bool HASBIAS, bool NCHK, bool DTSPLIT>
__global__ __launch_bounds__(256, 2)
void gemm_mma(const h16* __restrict__ Ahi, const h16* __restrict__ Alo,
              const h16* __restrict__ Bhi, const h16* __restrict__ Blo,
              const float* __restrict__ bias, float bias_scale,
              float* __restrict__ C, int N, int K, int Brows,
              h16* __restrict__ dth, h16* __restrict__ dtl)
{
    constexpr int MI     = BM / 32;          // m-iterations per warp
    constexpr int ABYTES = BM * 128;
    constexpr int STAGE  = ABYTES + 128 * 128;
    extern __shared__ char dsm[];
    const uint32_t base = (smem_u32(dsm) + 1023u) & ~1023u;

    const int tid    = threadIdx.x;
    const int rowBlk = blockIdx.y * BM;
    const int colBlk = blockIdx.x * 128;
    const int wid    = tid >> 5;
    const int lane   = tid & 31;
    const int warp_m = wid >> 2;          // 0..1 -> BM/2 rows
    const int warp_n = wid & 3;           // 0..3 -> 32 cols
    const int mat    = lane >> 3;
    const int rin    = lane & 7;

    const int KC     = K / 64;
    const int CHUNKS = NSTREAM * KC;

    // ldmatrix offsets, rows are 128B (64 halves), c = 16B chunk index 0..7
    uint32_t offA[MI][4], offB[2][4];
    #pragma unroll
    for (int mi = 0; mi < MI; mi++)
        #pragma unroll
        for (int j = 0; j < 4; j++) {
            int row = warp_m * (BM / 2) + mi * 16 + (mat & 1) * 8 + rin;
            int c   = 2 * j + (mat >> 1);
            offA[mi][j] = row * 128 + ((c ^ (row & 7)) << 4);
        }
    #pragma unroll
    for (int bi = 0; bi < 2; bi++)
        #pragma unroll
        for (int j = 0; j < 4; j++) {
            int row = warp_n * 32 + bi * 16 + (mat >> 1) * 8 + rin;
            int c   = 2 * j + (mat & 1);
            offB[bi][j] = ABYTES + row * 128 + ((c ^ (row & 7)) << 4);
        }

    float acc[MI][4][4];
    #pragma unroll
    for (int i = 0; i < MI; i++)
        #pragma unroll
        for (int j = 0; j < 4; j++)
            #pragma unroll
            for (int q = 0; q < 4; q++) acc[i][j][q] = 0.0f;

    auto load_stage = [&](int s, int c) {
        int stream = (c >= 2 * KC) ? 2 : ((c >= KC) ? 1 : 0);
        int k0 = (c - stream * KC) * 64;
        const h16* Ap;
        const h16* Bp;
        if (NSTREAM == 2) {
            Ap = stream ? Alo : Ahi;
            Bp = Bhi;
        } else {
            Ap = (stream == 2) ? Alo : Ahi;
            Bp = (stream == 1) ? Blo : Bhi;
        }
        uint32_t as_ = base + s * STAGE;
        uint32_t bs_ = as_ + ABYTES;
        #pragma unroll
        for (int t = 0; t < BM / 32; t++) {          // BM rows x 8 chunks
            int idx = tid + t * 256;
            int r = idx >> 3, cc = idx & 7;
            uint32_t dst = as_ + r * 128 + ((cc ^ (r & 7)) << 4);
            const char* src =
                (const char*)(Ap + (size_t)(rowBlk + r) * K + k0) + cc * 16;
            CP16(dst, src);
        }
        #pragma unroll
        for (int t = 0; t < 4; t++) {                // 128 rows x 8 chunks
            int idx = tid + t * 256;
            int r = idx >> 3, cc = idx & 7;
            uint32_t dst = bs_ + r * 128 + ((cc ^ (r & 7)) << 4);
            if (NCHK) {
                int br = colBlk + r;
                int ok = (br < Brows);
                const char* src =
                    (const char*)(Bp + (size_t)(ok ? br : 0) * K + k0) + cc * 16;
                CP16Z(dst, src, ok ? 16u : 0u);
            } else {
                const char* src =
                    (const char*)(Bp + (size_t)(colBlk + r) * K + k0) + cc * 16;
                CP16(dst, src);
            }
        }
    };

    // prologue: 2 chunks in flight
    load_stage(0, 0); CP_COMMIT();
    load_stage(1, 1); CP_COMMIT();

    int slot = 0;
    #pragma unroll 1
    for (int i = 0; i < CHUNKS; i++) {
        CP_WAIT1();              // chunk i landed (1 newer group pending)
        __syncthreads();         // also: all warps done reading slot (i+2)%3
        if (i + 2 < CHUNKS) {
            int s2 = slot + 2; if (s2 >= 3) s2 -= 3;
            load_stage(s2, i + 2);
        }
        CP_COMMIT();             // keep one group per iteration (may be empty)

        const uint32_t sb = base + slot * STAGE;
        #pragma unroll
        for (int j = 0; j < 4; j++) {
            uint32_t Af[MI][4];
            #pragma unroll
            for (int mi = 0; mi < MI; mi++) ldsm4(Af[mi], sb + offA[mi][j]);
            uint32_t Bf[4][2];
            #pragma unroll
            for (int bi = 0; bi < 2; bi++) {
                uint32_t r[4];
                ldsm4(r, sb + offB[bi][j]);
                Bf[bi * 2 + 0][0] = r[0]; Bf[bi * 2 + 0][1] = r[1];
                Bf[bi * 2 + 1][0] = r[2]; Bf[bi * 2 + 1][1] = r[3];
            }
            #pragma unroll
            for (int mi = 0; mi < MI; mi++)
                #pragma unroll
                for (int ni = 0; ni < 4; ni++)
                    mma16816(acc[mi][ni], Af[mi], Bf[ni]);
        }
        slot = (slot == 2) ? 0 : slot + 1;
    }

    // epilogue
    const int mrow = rowBlk + warp_m * (BM / 2) + (lane >> 2);
    const int ncol = colBlk + warp_n * 32 + (lane & 3) * 2;
    #pragma unroll
    for (int mi = 0; mi < MI; mi++) {
        #pragma unroll
        for (int ni = 0; ni < 4; ni++) {
            int n0 = ncol + ni * 8;
            if (NCHK && n0 >= Brows) continue;
            float v0 = acc[mi][ni][0], v1 = acc[mi][ni][1];
            float v2 = acc[mi][ni][2], v3 = acc[mi][ni][3];
            if (HASBIAS) {
                float b0 = bias_scale * __ldg(bias + n0);
                float b1 = bias_scale * __ldg(bias + n0 + 1);
                v0 += b0; v1 += b1; v2 += b0; v3 += b1;
            }
            if (SOFTPLUS) {
                v0 = softplus_f(v0); v1 = softplus_f(v1);
                v2 = softplus_f(v2); v3 = softplus_f(v3);
            }
            size_t r0 = (size_t)(mrow + mi * 16) * N + n0;
            size_t r1 = (size_t)(mrow + mi * 16 + 8) * N + n0;
            *reinterpret_cast<float2*>(C + r0) = make_float2(v0, v1);
            *reinterpret_cast<float2*>(C + r1) = make_float2(v2, v3);
            if (DTSPLIT && n0 < DTRANK) {
                h16 hh, ll;
                size_t d0 = (size_t)(mrow + mi * 16) * DTRANK + n0;
                size_t d1 = (size_t)(mrow + mi * 16 + 8) * DTRANK + n0;
                split_h16(v0, hh, ll); dth[d0] = hh;     dtl[d0] = ll;
                split_h16(v1, hh, ll); dth[d0 + 1] = hh; dtl[d0 + 1] = ll;
                split_h16(v2, hh, ll); dth[d1] = hh;     dtl[d1] = ll;
                split_h16(v3, hh, ll); dth[d1 + 1] = hh; dtl[d1 + 1] = ll;
            }
        }
    }
}

// ---------------------------------------------------------------------------
// fp32 -> fp16 hi/lo split (contiguous)
// ---------------------------------------------------------------------------
__global__ __launch_bounds__(256)
void split_kernel(const float* __restrict__ in, h16* __restrict__ oh,
                  h16* __restrict__ ol, int n)
{
    int i = (blockIdx.x * blockDim.x + threadIdx.x) * 4;
    if (i >= n) return;
    float4 v = *reinterpret_cast<const float4*>(in + i);
    h16 h0, l0, h1, l1, h2, l2, h3, l3;
    split_h16(v.x, h0, l0); split_h16(v.y, h1, l1);
    split_h16(v.z, h2, l2); split_h16(v.w, h3, l3);
    __half2* ph = reinterpret_cast<__half2*>(oh + i);
    __half2* pl = reinterpret_cast<__half2*>(ol + i);
    ph[0] = __half2(h0, h1); ph[1] = __half2(h2, h3);
    pl[0] = __half2(l0, l1); pl[1] = __half2(l2, l3);
}

// transpose + split:  in [R,C] fp32 -> out [C,R] fp16 hi (+lo if WRITELO)
template <bool WRITELO>
__global__ __launch_bounds__(256)
void tsplit_kernel(const float* __restrict__ in, h16* __restrict__ oh,
                   h16* __restrict__ ol, int R, int C)
{
    __shared__ float t[32][33];
    const int cx = blockIdx.x * 32, ry = blockIdx.y * 32;
    const int tx = threadIdx.x, ty = threadIdx.y;   // 32 x 8
    #pragma unroll
    for (int j = ty; j < 32; j += 8)
        t[j][tx] = in[(size_t)(ry + j) * C + cx + tx];
    __syncthreads();
    #pragma unroll
    for (int j = ty; j < 32; j += 8) {
        float v = t[tx][j];
        h16 h, l; split_h16(v, h, l);
        size_t o = (size_t)(cx + j) * R + ry + tx;
        oh[o] = h;
        if (WRITELO) ol[o] = l;
    }
}

// ---------------------------------------------------------------------------
// Depthwise conv (k=4, SAME: pad left 1, right 2) + SiLU
// x-half: writes split fp16 only (scan reconstructs u = hi + lo)
// ---------------------------------------------------------------------------
__global__ __launch_bounds__(256)
void conv_x_kernel(const float* __restrict__ xz,
                   const float* __restrict__ w, const float* __restrict__ bias,
                   h16* __restrict__ oh, h16* __restrict__ ol)
{
    int idx = blockIdx.x * blockDim.x + threadIdx.x;
    int c = idx & (DHALF - 1);
    int bl = idx >> 10;
    int l = bl & (LSEQ - 1);
    float acc = bias[c];
    const float* src = xz + (size_t)bl * DINNER + c;
    #pragma unroll
    for (int j = 0; j < 4; j++) {
        int ll = l + j - 1;
        if (ll >= 0 && ll < LSEQ)
            acc = fmaf(src[(ptrdiff_t)(j - 1) * DINNER], w[j * DHALF + c], acc);
    }
    float v = silu_f(acc);
    h16 h, lo; split_h16(v, h, lo);
    oh[idx] = h; ol[idx] = lo;
}

// z-half: conv + silu, write split fp16 directly into concat right half
__global__ __launch_bounds__(256)
void conv_z_kernel(const float* __restrict__ xz,
                   const float* __restrict__ w, const float* __restrict__ bias,
                   h16* __restrict__ cat_h, h16* __restrict__ cat_l)
{
    int idx = blockIdx.x * blockDim.x + threadIdx.x;
    int c = idx & (DHALF - 1);
    int bl = idx >> 10;
    int l = bl & (LSEQ - 1);
    float acc = bias[c];
    const float* src = xz + (size_t)bl * DINNER + DHALF + c;
    #pragma unroll
    for (int j = 0; j < 4; j++) {
        int ll = l + j - 1;
        if (ll >= 0 && ll < LSEQ)
            acc = fmaf(src[(ptrdiff_t)(j - 1) * DINNER], w[j * DHALF + c], acc);
    }
    float v = silu_f(acc);
    h16 h, lo; split_h16(v, h, lo);
    size_t o = (size_t)bl * DINNER + DHALF + c;
    cat_h[o] = h; cat_l[o] = lo;
}

// ---------------------------------------------------------------------------
// Chunk-parallel selective scan.  A[d][n] = -(n+1) => dA_n = exp(-delta)^(n+1).
//   Phase 1: per (b, chunk, dblk) compute q and S = Sum(delta).   512 blocks
//   Phase 2: per (b, d) sequential combine over 16 chunks -> h_start.
//   Phase 3: replay each chunk from its h_start, emit y.          512 blocks
// u is reconstructed from the fp16 split pair (exact to 2^-22).
// ---------------------------------------------------------------------------
#define PW16(p1, pw)                                                    \
    float p2 = (p1) * (p1), p3 = p2 * (p1), p4 = p2 * p2;               \
    float p5 = p4 * (p1), p6 = p4 * p2, p7 = p4 * p3, p8 = p4 * p4;     \
    float pw[16] = {(p1), p2, p3, p4, p5, p6, p7, p8,                   \
                    p8 * (p1), p8 * p2, p8 * p3, p8 * p4,               \
                    p8 * p5, p8 * p6, p8 * p7, p8 * p8};

__global__ __launch_bounds__(128)
void scan_p1(const float* __restrict__ delta,
             const h16* __restrict__ uh, const h16* __restrict__ ul,
             const float* __restrict__ xdbl,
             float* __restrict__ q, float* __restrict__ S)
{
    const int tid = threadIdx.x;
    const int chunk = blockIdx.x, dblk = blockIdx.y, b = blockIdx.z;
    const int d = (dblk << 7) + tid;

    __shared__ float sB[16][DSTATE];
    __shared__ float sd[16][128];
    __shared__ float su[16][128];

    float h[DSTATE];
    #pragma unroll
    for (int n = 0; n < DSTATE; n++) h[n] = 0.0f;
    float sum = 0.0f;
    const size_t baseRow = (size_t)b * LSEQ + (size_t)chunk * LCHUNK;

    for (int t0 = 0; t0 < LCHUNK; t0 += 16) {
        {
            int s = tid >> 3;
            int i = (tid & 7) << 1;
            float2 v = *reinterpret_cast<const float2*>(
                xdbl + (baseRow + t0 + s) * XDBL_N + DTRANK + i);
            sB[s][i] = v.x; sB[s][i + 1] = v.y;
        }
        #pragma unroll
        for (int s = 0; s < 16; s++) {
            size_t r = (baseRow + t0 + s) * DHALF + d;
            sd[s][tid] = delta[r];
            su[s][tid] = __half2float(uh[r]) + __half2float(ul[r]);
        }
        __syncthreads();

        #pragma unroll
        for (int s = 0; s < 16; s++) {
            float dl = sd[s][tid];
            float du = dl * su[s][tid];
            sum += dl;
            float p1 = __expf(-dl);
            PW16(p1, pw)
            #pragma unroll
            for (int n = 0; n < DSTATE; n++)
                h[n] = fmaf(pw[n], h[n], du * sB[s][n]);
        }
        __syncthreads();
    }
    const size_t cbase = ((size_t)(b * NCHUNK + chunk) * DSTATE) * DHALF + d;
    #pragma unroll
    for (int n = 0; n < DSTATE; n++) q[cbase + (size_t)n * DHALF] = h[n];
    S[(size_t)(b * NCHUNK + chunk) * DHALF + d] = sum;
}

__global__ __launch_bounds__(128)
void scan_p2(const float* __restrict__ q, const float* __restrict__ S,
             float* __restrict__ hs)
{
    const int idx = blockIdx.x * 128 + threadIdx.x;   // < 4096
    const int b = idx >> 10, d = idx & (DHALF - 1);
    float h[DSTATE];
    #pragma unroll
    for (int n = 0; n < DSTATE; n++) h[n] = 0.0f;
    for (int c = 0; c < NCHUNK; c++) {
        const size_t cbase = ((size_t)(b * NCHUNK + c) * DSTATE) * DHALF + d;
        #pragma unroll
        for (int n = 0; n < DSTATE; n++) hs[cbase + (size_t)n * DHALF] = h[n];
        float s = S[(size_t)(b * NCHUNK + c) * DHALF + d];
        float p1 = __expf(-s);
        PW16(p1, pw)
        #pragma unroll
        for (int n = 0; n < DSTATE; n++)
            h[n] = fmaf(pw[n], h[n], q[cbase + (size_t)n * DHALF]);
    }
}

__global__ __launch_bounds__(128)
void scan_p3(const float* __restrict__ delta,
             const h16* __restrict__ uh, const h16* __restrict__ ul,
             const float* __restrict__ xdbl, const float* __restrict__ hs,
             const float* __restrict__ Dv,
             h16* __restrict__ cat_h, h16* __restrict__ cat_l)
{
    const int tid = threadIdx.x;
    const int chunk = blockIdx.x, dblk = blockIdx.y, b = blockIdx.z;
    const int d = (dblk << 7) + tid;

    __shared__ float sB[16][DSTATE];
    __shared__ float sC[16][DSTATE];
    __shared__ float sd[16][128];
    __shared__ float su[16][128];

    float h[DSTATE];
    const size_t cbase = ((size_t)(b * NCHUNK + chunk) * DSTATE) * DHALF + d;
    #pragma unroll
    for (int n = 0; n < DSTATE; n++) h[n] = hs[cbase + (size_t)n * DHALF];
    const float Dd = Dv[d];
    const size_t baseRow = (size_t)b * LSEQ + (size_t)chunk * LCHUNK;

    for (int t0 = 0; t0 < LCHUNK; t0 += 16) {
        {
            int s = tid >> 3;
            int i = (tid & 7) << 2;
            float4 v = *reinterpret_cast<const float4*>(
                xdbl + (baseRow + t0 + s) * XDBL_N + DTRANK + i);
            float vv[4] = {v.x, v.y, v.z, v.w};
            #pragma unroll
            for (int qq = 0; qq < 4; qq++) {
                int ii = i + qq;
                if (ii < DSTATE) sB[s][ii] = vv[qq];
                else             sC[s][ii - DSTATE] = vv[qq];
            }
        }
        #pragma unroll
        for (int s = 0; s < 16; s++) {
            size_t r = (baseRow + t0 + s) * DHALF + d;
            sd[s][tid] = delta[r];
            su[s][tid] = __half2float(uh[r]) + __half2float(ul[r]);
        }
        __syncthreads();

        #pragma unroll
        for (int s = 0; s < 16; s++) {
            float dl = sd[s][tid];
            float uu = su[s][tid];
            float du = dl * uu;
            float p1 = __expf(-dl);
            PW16(p1, pw)
            float y0 = 0.f, y1 = 0.f, y2 = 0.f, y3 = 0.f;
            #pragma unroll
            for (int n = 0; n < DSTATE; n += 4) {
                h[n + 0] = fmaf(pw[n + 0], h[n + 0], du * sB[s][n + 0]);
                h[n + 1] = fmaf(pw[n + 1], h[n + 1], du * sB[s][n + 1]);
                h[n + 2] = fmaf(pw[n + 2], h[n + 2], du * sB[s][n + 2]);
                h[n + 3] = fmaf(pw[n + 3], h[n + 3], du * sB[s][n + 3]);
                y0 = fmaf(h[n + 0], sC[s][n + 0], y0);
                y1 = fmaf(h[n + 1], sC[s][n + 1], y1);
                y2 = fmaf(h[n + 2], sC[s][n + 2], y2);
                y3 = fmaf(h[n + 3], sC[s][n + 3], y3);
            }
            float yv = fmaf(uu, Dd, (y0 + y1) + (y2 + y3));
            h16 hh, ll; split_h16(yv, hh, ll);
            size_t o = (baseRow + t0 + s) * DINNER + d;
            cat_h[o] = hh; cat_l[o] = ll;
        }
        __syncthreads();
    }
}

// ---------------------------------------------------------------------------
// Launch
// ---------------------------------------------------------------------------
extern "C" void kernel_launch(void* const* d_in, const int* in_sizes, int n_in,
                              void* d_out, int out_size)
{
    const float* x        = (const float*)d_in[0];
    const float* W_in     = (const float*)d_in[1];
    const float* conv_x_w = (const float*)d_in[2];
    const float* conv_x_b = (const float*)d_in[3];
    const float* conv_z_w = (const float*)d_in[4];
    const float* conv_z_b = (const float*)d_in[5];
    const float* W_xdbl   = (const float*)d_in[6];
    const float* W_dt     = (const float*)d_in[7];
    const float* inv_dt   = (const float*)d_in[8];
    const float* Dvec     = (const float*)d_in[9];
    const float* W_out    = (const float*)d_in[10];
    const float* b_out    = (const float*)d_in[11];
    float* out            = (float*)d_out;

    float *p_xz, *p_xdbl, *p_delta, *p_q, *p_hs, *p_S;
    h16 *p_a1h, *p_a1l, *p_b1h, *p_xsh, *p_xsl, *p_bxh, *p_bxl;
    h16 *p_dth, *p_dtl, *p_bdh, *p_bdl, *p_ch, *p_cl, *p_b2h;
    cudaGetSymbolAddress((void**)&p_xz,    g_xz);
    cudaGetSymbolAddress((void**)&p_xdbl,  g_xdbl);
    cudaGetSymbolAddress((void**)&p_delta, g_delta);
    cudaGetSymbolAddress((void**)&p_q,  g_q);
    cudaGetSymbolAddress((void**)&p_hs, g_hs);
    cudaGetSymbolAddress((void**)&p_S,  g_S);
    cudaGetSymbolAddress((void**)&p_a1h, g_a1h); cudaGetSymbolAddress((void**)&p_a1l, g_a1l);
    cudaGetSymbolAddress((void**)&p_b1h, g_b1h);
    cudaGetSymbolAddress((void**)&p_xsh, g_xsh); cudaGetSymbolAddress((void**)&p_xsl, g_xsl);
    cudaGetSymbolAddress((void**)&p_bxh, g_bxh); cudaGetSymbolAddress((void**)&p_bxl, g_bxl);
    cudaGetSymbolAddress((void**)&p_dth, g_dth); cudaGetSymbolAddress((void**)&p_dtl, g_dtl);
    cudaGetSymbolAddress((void**)&p_bdh, g_bdh); cudaGetSymbolAddress((void**)&p_bdl, g_bdl);
    cudaGetSymbolAddress((void**)&p_ch,  g_ch);  cudaGetSymbolAddress((void**)&p_cl,  g_cl);
    cudaGetSymbolAddress((void**)&p_b2h, g_b2h);

    constexpr int SMEM128 = 3 * (128 * 128 + 128 * 128) + 1024;   // 99328
    constexpr int SMEM32  = 3 * (32 * 128 + 128 * 128) + 1024;    // 62464
    cudaFuncSetAttribute((const void*)gemm_mma<128,2,false,false,false,false>,
                         cudaFuncAttributeMaxDynamicSharedMemorySize, SMEM128);
    cudaFuncSetAttribute((const void*)gemm_mma<128,3,true,true,false,false>,
                         cudaFuncAttributeMaxDynamicSharedMemorySize, SMEM128);
    cudaFuncSetAttribute((const void*)gemm_mma<128,2,false,true,false,false>,
                         cudaFuncAttributeMaxDynamicSharedMemorySize, SMEM128);
    cudaFuncSetAttribute((const void*)gemm_mma<32,3,false,false,true,true>,
                         cudaFuncAttributeMaxDynamicSharedMemorySize, SMEM32);

    // 1) weight transposes + splits (lo skipped where 2-stream GEMMs ignore it)
    tsplit_kernel<false><<<dim3(DINNER / 32, DMODEL / 32), dim3(32, 8)>>>(W_in,   p_b1h, nullptr, DMODEL, DINNER);
    tsplit_kernel<true ><<<dim3(XDBL_N / 32, DHALF / 32),  dim3(32, 8)>>>(W_xdbl, p_bxh, p_bxl, DHALF,  XDBL_N);
    tsplit_kernel<true ><<<dim3(DHALF / 32, DTRANK / 32),  dim3(32, 8)>>>(W_dt,   p_bdh, p_bdl, DTRANK, DHALF);
    tsplit_kernel<false><<<dim3(DMODEL / 32, DINNER / 32), dim3(32, 8)>>>(W_out,  p_b2h, nullptr, DINNER, DMODEL);

    // 2) split x
    split_kernel<<<(MROWS * DMODEL / 4) / 256, 256>>>(x, p_a1h, p_a1l, MROWS * DMODEL);

    // 3) xz = x @ W_in                              [8192,2048]  (2-stream)
    gemm_mma<128,2,false,false,false,false><<<dim3(DINNER / 128, MROWS / 128), 256, SMEM128>>>(
        p_a1h, p_a1l, p_b1h, nullptr, nullptr, 0.0f, p_xz, DINNER, DMODEL, DINNER,
        nullptr, nullptr);

    // 4) depthwise convs + silu (split fp16 outputs)
    conv_x_kernel<<<(MROWS * DHALF) / 256, 256>>>(p_xz, conv_x_w, conv_x_b, p_xsh, p_xsl);
    conv_z_kernel<<<(MROWS * DHALF) / 256, 256>>>(p_xz, conv_z_w, conv_z_b, p_ch, p_cl);

    // 5) x_dbl = xs @ W_xdbl  [8192,96] (3-stream, BM=32 -> 256 CTAs full chip)
    gemm_mma<32,3,false,false,true,true><<<dim3(1, MROWS / 32), 256, SMEM32>>>(
        p_xsh, p_xsl, p_bxh, p_bxl, nullptr, 0.0f, p_xdbl, XDBL_N, DHALF, XDBL_N,
        p_dth, p_dtl);

    // 6) delta = softplus(dt_low @ W_dt + 2*inv_dt) [8192,1024] (3-stream)
    gemm_mma<128,3,true,true,false,false><<<dim3(DHALF / 128, MROWS / 128), 256, SMEM128>>>(
        p_dth, p_dtl, p_bdh, p_bdl, inv_dt, 2.0f, p_delta, DHALF, DTRANK, DHALF,
        nullptr, nullptr);

    // 7) chunk-parallel selective scan -> concat left half (split fp16)
    scan_p1<<<dim3(NCHUNK, 8, B_SZ), 128>>>(p_delta, p_xsh, p_xsl, p_xdbl, p_q, p_S);
    scan_p2<<<32, 128>>>(p_q, p_S, p_hs);
    scan_p3<<<dim3(NCHUNK, 8, B_SZ), 128>>>(p_delta, p_xsh, p_xsl, p_xdbl, p_hs, Dvec, p_ch, p_cl);

    // 8) out = [y|z] @ W_out + b_out                [8192,1024]  (2-stream)
    gemm_mma<128,2,false,true,false,false><<<dim3(DMODEL / 128, MROWS / 128), 256, SMEM128>>>(
        p_ch, p_cl, p_b2h, nullptr, b_out, 1.0f, out, DMODEL, DINNER, DMODEL,
        nullptr, nullptr);
}

// round 8
// speedup vs baseline: 1.0538x; 1.0538x over previous
#include <cuda_runtime.h>
#include <cuda_fp16.h>
#include <cstdint>
#include <cstddef>

// ---------------------------------------------------------------------------
// Problem constants (MambaVisionMixer, B=4, L=2048)
// ---------------------------------------------------------------------------
#define B_SZ    4
#define LSEQ    2048
#define DMODEL  1024
#define DINNER  2048
#define DHALF   1024
#define DSTATE  16
#define DTRANK  64
#define XDBL_N  96
#define MROWS   (B_SZ*LSEQ)   // 8192
#define NCHUNK  16
#define LCHUNK  (LSEQ/NCHUNK) // 128

typedef __half h16;

// ---------------------------------------------------------------------------
// Device scratch (static __device__ arrays — no allocations)
// ---------------------------------------------------------------------------
__device__ float g_xz   [(size_t)MROWS * DINNER];   // 64 MB
__device__ float g_xdbl [(size_t)MROWS * XDBL_N];   // 3 MB
__device__ float g_delta[(size_t)MROWS * DHALF];    // 32 MB

__device__ float g_q [(size_t)B_SZ * NCHUNK * DSTATE * DHALF];  // 4 MB
__device__ float g_hs[(size_t)B_SZ * NCHUNK * DSTATE * DHALF];  // 4 MB
__device__ float g_S [(size_t)B_SZ * NCHUNK * DHALF];           // 256 KB

__device__ h16 g_a1h[(size_t)MROWS * DMODEL];      // x hi
__device__ h16 g_a1l[(size_t)MROWS * DMODEL];      // x lo
__device__ h16 g_b1h[(size_t)DINNER * DMODEL];     // W_in^T hi  [2048,1024]
__device__ h16 g_xsh[(size_t)MROWS * DHALF];       // xs hi
__device__ h16 g_xsl[(size_t)MROWS * DHALF];       // xs lo
__device__ h16 g_bxh[(size_t)XDBL_N * DHALF];      // W_xdbl^T [96,1024]
__device__ h16 g_bxl[(size_t)XDBL_N * DHALF];
__device__ h16 g_dth[(size_t)MROWS * DTRANK];      // dt_low hi [8192,64]
__device__ h16 g_dtl[(size_t)MROWS * DTRANK];
__device__ h16 g_bdh[(size_t)DHALF * DTRANK];      // W_dt^T [1024,64]
__device__ h16 g_bdl[(size_t)DHALF * DTRANK];
__device__ h16 g_ch [(size_t)MROWS * DINNER];      // [y|z] hi [8192,2048]
__device__ h16 g_cl [(size_t)MROWS * DINNER];
__device__ h16 g_b2h[(size_t)DMODEL * DINNER];     // W_out^T [1024,2048]

// ---------------------------------------------------------------------------
// Helpers (sm_80-era ISA only: compiles at compute_103 non-'a' target)
// ---------------------------------------------------------------------------
__device__ __forceinline__ uint32_t smem_u32(const void* p) {
    uint32_t r;
    asm("{ .reg .u64 t; cvta.to.shared.u64 t, %1; cvt.u32.u64 %0, t; }"
        : "=r"(r) : "l"(p));
    return r;
}

#define CP16(dst, src) \
    asm volatile("cp.async.cg.shared.global [%0], [%1], 16;" \
        :: "r"(dst), "l"(src) : "memory")
#define CP16Z(dst, src, sz) \
    asm volatile("cp.async.cg.shared.global [%0], [%1], 16, %2;" \
        :: "r"(dst), "l"(src), "r"(sz) : "memory")
#define CP_COMMIT() asm volatile("cp.async.commit_group;" ::: "memory")
#define CP_WAIT2()  asm volatile("cp.async.wait_group 2;" ::: "memory")
#define CP_WAIT1()  asm volatile("cp.async.wait_group 1;" ::: "memory")

__device__ __forceinline__ void ldsm4(uint32_t* r, uint32_t addr) {
    asm volatile("ldmatrix.sync.aligned.m8n8.x4.shared.b16 {%0,%1,%2,%3}, [%4];"
        : "=r"(r[0]), "=r"(r[1]), "=r"(r[2]), "=r"(r[3]) : "r"(addr));
}

__device__ __forceinline__ void mma16816(float* d, const uint32_t* a,
                                         const uint32_t* b) {
    asm volatile(
        "mma.sync.aligned.m16n8k16.row.col.f32.f16.f16.f32 "
        "{%0,%1,%2,%3}, {%4,%5,%6,%7}, {%8,%9}, {%0,%1,%2,%3};"
        : "+f"(d[0]), "+f"(d[1]), "+f"(d[2]), "+f"(d[3])
        : "r"(a[0]), "r"(a[1]), "r"(a[2]), "r"(a[3]), "r"(b[0]), "r"(b[1]));
}

__device__ __forceinline__ float softplus_f(float x) {
    return fmaxf(x, 0.0f) + log1pf(expf(-fabsf(x)));
}
__device__ __forceinline__ float silu_f(float x) {
    return x / (1.0f + expf(-x));
}
__device__ __forceinline__ void split_h16(float v, h16& h, h16& l) {
    h = __float2half_rn(v);
    l = __float2half_rn(v - __half2float(h));
}

// ---------------------------------------------------------------------------
// 2-stream shared-B GEMM (mma.sync fp16, fp32 accum):
//   C[M,N] = (Ahi+Alo)[M,K] @ Bhi^T   (B stored [N,K] row-major)
//   Each k-chunk stage holds {Ahi, Alo, B}; B tile is loaded ONCE and used by
//   both A-stream passes (halves B L2 traffic and chunk count vs extended-K).
//   CTA 128x128, 8 warps (2x4), warp tile 64x32, BK=64, 2-stage cp.async.
//   Smem rows 128B; SW128 swizzle chunk c ^= row&7 -> conflict-free ldmatrix.
// ---------------------------------------------------------------------------
template <bool SOFTPLUS, bool HASBIAS>
__global__ __launch_bounds__(256, 2)
void gemm_mma2(const h16* __restrict__ Ahi, const h16* __restrict__ Alo,
               const h16* __restrict__ Bhi,
               const float* __restrict__ bias, float bias_scale,
               float* __restrict__ C, int N, int K)
{
    constexpr int BM     = 128;
    constexpr int MI     = 4;
    constexpr int ABYTES = BM * 128;                 // 16 KB per A stream
    constexpr int STAGE  = 2 * ABYTES + 128 * 128;   // 48 KB
    extern __shared__ char dsm[];
    const uint32_t base = (smem_u32(dsm) + 1023u) & ~1023u;

    const int tid    = threadIdx.x;
    const int rowBlk = blockIdx.y * BM;
    const int colBlk = blockIdx.x * 128;
    const int wid    = tid >> 5;
    const int lane   = tid & 31;
    const int warp_m = wid >> 2;
    const int warp_n = wid & 3;
    const int mat    = lane >> 3;
    const int rin    = lane & 7;

    const int CHUNKS = K / 64;

    uint32_t offA[MI][4], offB[2][4];
    #pragma unroll
    for (int mi = 0; mi < MI; mi++)
        #pragma unroll
        for (int j = 0; j < 4; j++) {
            int row = warp_m * 64 + mi * 16 + (mat & 1) * 8 + rin;
            int c   = 2 * j + (mat >> 1);
            offA[mi][j] = row * 128 + ((c ^ (row & 7)) << 4);
        }
    #pragma unroll
    for (int bi = 0; bi < 2; bi++)
        #pragma unroll
        for (int j = 0; j < 4; j++) {
            int row = warp_n * 32 + bi * 16 + (mat >> 1) * 8 + rin;
            int c   = 2 * j + (mat & 1);
            offB[bi][j] = 2 * ABYTES + row * 128 + ((c ^ (row & 7)) << 4);
        }

    float acc[MI][4][4];
    #pragma unroll
    for (int i = 0; i < MI; i++)
        #pragma unroll
        for (int j = 0; j < 4; j++)
            #pragma unroll
            for (int q = 0; q < 4; q++) acc[i][j][q] = 0.0f;

    auto load_stage = [&](int s, int c) {
        int k0 = c * 64;
        uint32_t st = base + s * STAGE;
        #pragma unroll
        for (int t = 0; t < 4; t++) {               // Ahi: 128 rows x 8 chunks
            int idx = tid + t * 256;
            int r = idx >> 3, cc = idx & 7;
            uint32_t sw = r * 128 + ((cc ^ (r & 7)) << 4);
            const char* srcH =
                (const char*)(Ahi + (size_t)(rowBlk + r) * K + k0) + cc * 16;
            const char* srcL =
                (const char*)(Alo + (size_t)(rowBlk + r) * K + k0) + cc * 16;
            CP16(st + sw, srcH);
            CP16(st + ABYTES + sw, srcL);
        }
        #pragma unroll
        for (int t = 0; t < 4; t++) {               // B: 128 rows x 8 chunks
            int idx = tid + t * 256;
            int r = idx >> 3, cc = idx & 7;
            uint32_t sw = r * 128 + ((cc ^ (r & 7)) << 4);
            const char* src =
                (const char*)(Bhi + (size_t)(colBlk + r) * K + k0) + cc * 16;
            CP16(st + 2 * ABYTES + sw, src);
        }
    };

    // prologue: 2 chunks in flight
    load_stage(0, 0); CP_COMMIT();
    load_stage(1, 1); CP_COMMIT();

    #pragma unroll 1
    for (int i = 0; i < CHUNKS; i++) {
        const int slot = i & 1;
        CP_WAIT1();              // chunk i landed
        __syncthreads();
        const uint32_t sb = base + slot * STAGE;
        // two passes over the same B tile: A-hi then A-lo
        #pragma unroll
        for (int pass = 0; pass < 2; pass++) {
            const uint32_t ab = sb + pass * ABYTES;
            #pragma unroll
            for (int j = 0; j < 4; j++) {
                uint32_t Af[MI][4];
                #pragma unroll
                for (int mi = 0; mi < MI; mi++) ldsm4(Af[mi], ab + offA[mi][j]);
                uint32_t Bf[4][2];
                #pragma unroll
                for (int bi = 0; bi < 2; bi++) {
                    uint32_t r[4];
                    ldsm4(r, sb + offB[bi][j]);
                    Bf[bi * 2 + 0][0] = r[0]; Bf[bi * 2 + 0][1] = r[1];
                    Bf[bi * 2 + 1][0] = r[2]; Bf[bi * 2 + 1][1] = r[3];
                }
                #pragma unroll
                for (int mi = 0; mi < MI; mi++)
                    #pragma unroll
                    for (int ni = 0; ni < 4; ni++)
                        mma16816(acc[mi][ni], Af[mi], Bf[ni]);
            }
        }
        __syncthreads();         // all warps done reading slot
        if (i + 2 < CHUNKS) load_stage(slot, i + 2);
        CP_COMMIT();
    }

    // epilogue
    const int mrow = rowBlk + warp_m * 64 + (lane >> 2);
    const int ncol = colBlk + warp_n * 32 + (lane & 3) * 2;
    #pragma unroll
    for (int mi = 0; mi < MI; mi++) {
        #pragma unroll
        for (int ni = 0; ni < 4; ni++) {
            int n0 = ncol + ni * 8;
            float v0 = acc[mi][ni][0], v1 = acc[mi][ni][1];
            float v2 = acc[mi][ni][2], v3 = acc[mi][ni][3];
            if (HASBIAS) {
                float b0 = bias_scale * __ldg(bias + n0);
                float b1 = bias_scale * __ldg(bias + n0 + 1);
                v0 += b0; v1 += b1; v2 += b0; v3 += b1;
            }
            if (SOFTPLUS) {
                v0 = softplus_f(v0); v1 = softplus_f(v1);
                v2 = softplus_f(v2); v3 = softplus_f(v3);
            }
            size_t r0 = (size_t)(mrow + mi * 16) * N + n0;
            size_t r1 = (size_t)(mrow + mi * 16 + 8) * N + n0;
            *reinterpret_cast<float2*>(C + r0) = make_float2(v0, v1);
            *reinterpret_cast<float2*>(C + r1) = make_float2(v2, v3);
        }
    }
}

// ---------------------------------------------------------------------------
// 3-stream extended-K GEMM (R6 mainloop: 3 stages, two syncs per chunk).
//   streams (Ahi,Bhi), (Ahi,Blo), (Alo,Bhi) -> error ~ 2^-22.
//   Used for the small GEMMs (xdbl, delta).
// ---------------------------------------------------------------------------
template <int BM, bool SOFTPLUS, bool HASBIAS, bool NCHK, bool DTSPLIT>
__global__ __launch_bounds__(256, 2)
void gemm_mma3(const h16* __restrict__ Ahi, const h16* __restrict__ Alo,
               const h16* __restrict__ Bhi, const h16* __restrict__ Blo,
               const float* __restrict__ bias, float bias_scale,
               float* __restrict__ C, int N, int K, int Brows,
               h16* __restrict__ dth, h16* __restrict__ dtl)
{
    constexpr int MI     = BM / 32;
    constexpr int ABYTES = BM * 128;
    constexpr int STAGE  = ABYTES + 128 * 128;
    extern __shared__ char dsm[];
    const uint32_t base = (smem_u32(dsm) + 1023u) & ~1023u;

    const int tid    = threadIdx.x;
    const int rowBlk = blockIdx.y * BM;
    const int colBlk = blockIdx.x * 128;
    const int wid    = tid >> 5;
    const int lane   = tid & 31;
    const int warp_m = wid >> 2;
    const int warp_n = wid & 3;
    const int mat    = lane >> 3;
    const int rin    = lane & 7;

    const int KC     = K / 64;
    const int CHUNKS = 3 * KC;

    uint32_t offA[MI][4], offB[2][4];
    #pragma unroll
    for (int mi = 0; mi < MI; mi++)
        #pragma unroll
        for (int j = 0; j < 4; j++) {
            int row = warp_m * (BM / 2) + mi * 16 + (mat & 1) * 8 + rin;
            int c   = 2 * j + (mat >> 1);
            offA[mi][j] = row * 128 + ((c ^ (row & 7)) << 4);
        }
    #pragma unroll
    for (int bi = 0; bi < 2; bi++)
        #pragma unroll
        for (int j = 0; j < 4; j++) {
            int row = warp_n * 32 + bi * 16 + (mat >> 1) * 8 + rin;
            int c   = 2 * j + (mat & 1);
            offB[bi][j] = ABYTES + row * 128 + ((c ^ (row & 7)) << 4);
        }

    float acc[MI][4][4];
    #pragma unroll
    for (int i = 0; i < MI; i++)
        #pragma unroll
        for (int j = 0; j < 4; j++)
            #pragma unroll
            for (int q = 0; q < 4; q++) acc[i][j][q] = 0.0f;

    auto load_stage = [&](int s, int c) {
        int stream = (c >= 2 * KC) ? 2 : ((c >= KC) ? 1 : 0);
        int k0 = (c - stream * KC) * 64;
        const h16* Ap = (stream == 2) ? Alo : Ahi;
        const h16* Bp = (stream == 1) ? Blo : Bhi;
        uint32_t as_ = base + s * STAGE;
        uint32_t bs_ = as_ + ABYTES;
        #pragma unroll
        for (int t = 0; t < BM / 32; t++) {
            int idx = tid + t * 256;
            int r = idx >> 3, cc = idx & 7;
            uint32_t dst = as_ + r * 128 + ((cc ^ (r & 7)) << 4);
            const char* src =
                (const char*)(Ap + (size_t)(rowBlk + r) * K + k0) + cc * 16;
            CP16(dst, src);
        }
        #pragma unroll
        for (int t = 0; t < 4; t++) {
            int idx = tid + t * 256;
            int r = idx >> 3, cc = idx & 7;
            uint32_t dst = bs_ + r * 128 + ((cc ^ (r & 7)) << 4);
            if (NCHK) {
                int br = colBlk + r;
                int ok = (br < Brows);
                const char* src =
                    (const char*)(Bp + (size_t)(ok ? br : 0) * K + k0) + cc * 16;
                CP16Z(dst, src, ok ? 16u : 0u);
            } else {
                const char* src =
                    (const char*)(Bp + (size_t)(colBlk + r) * K + k0) + cc * 16;
                CP16(dst, src);
            }
        }
    };

    #pragma unroll
    for (int s = 0; s < 3; s++) { load_stage(s, s); CP_COMMIT(); }

    int slot = 0;
    #pragma unroll 1
    for (int i = 0; i < CHUNKS; i++) {
        CP_WAIT2();
        __syncthreads();
        const uint32_t sb = base + slot * STAGE;
        #pragma unroll
        for (int j = 0; j < 4; j++) {
            uint32_t Af[MI][4];
            #pragma unroll
            for (int mi = 0; mi < MI; mi++) ldsm4(Af[mi], sb + offA[mi][j]);
            uint32_t Bf[4][2];
            #pragma unroll
            for (int bi = 0; bi < 2; bi++) {
                uint32_t r[4];
                ldsm4(r, sb + offB[bi][j]);
                Bf[bi * 2 + 0][0] = r[0]; Bf[bi * 2 + 0][1] = r[1];
                Bf[bi * 2 + 1][0] = r[2]; Bf[bi * 2 + 1][1] = r[3];
            }
            #pragma unroll
            for (int mi = 0; mi < MI; mi++)
                #pragma unroll
                for (int ni = 0; ni < 4; ni++)
                    mma16816(acc[mi][ni], Af[mi], Bf[ni]);
        }
        __syncthreads();
        if (i + 3 < CHUNKS) load_stage(slot, i + 3);
        CP_COMMIT();
        slot = (slot == 2) ? 0 : slot + 1;
    }

    // epilogue
    const int mrow = rowBlk + warp_m * (BM / 2) + (lane >> 2);
    const int ncol = colBlk + warp_n * 32 + (lane & 3) * 2;
    #pragma unroll
    for (int mi = 0; mi < MI; mi++) {
        #pragma unroll
        for (int ni = 0; ni < 4; ni++) {
            int n0 = ncol + ni * 8;
            if (NCHK && n0 >= Brows) continue;
            float v0 = acc[mi][ni][0], v1 = acc[mi][ni][1];
            float v2 = acc[mi][ni][2], v3 = acc[mi][ni][3];
            if (HASBIAS) {
                float b0 = bias_scale * __ldg(bias + n0);
                float b1 = bias_scale * __ldg(bias + n0 + 1);
                v0 += b0; v1 += b1; v2 += b0; v3 += b1;
            }
            if (SOFTPLUS) {
                v0 = softplus_f(v0); v1 = softplus_f(v1);
                v2 = softplus_f(v2); v3 = softplus_f(v3);
            }
            size_t r0 = (size_t)(mrow + mi * 16) * N + n0;
            size_t r1 = (size_t)(mrow + mi * 16 + 8) * N + n0;
            *reinterpret_cast<float2*>(C + r0) = make_float2(v0, v1);
            *reinterpret_cast<float2*>(C + r1) = make_float2(v2, v3);
            if (DTSPLIT && n0 < DTRANK) {
                h16 hh, ll;
                size_t d0 = (size_t)(mrow + mi * 16) * DTRANK + n0;
                size_t d1 = (size_t)(mrow + mi * 16 + 8) * DTRANK + n0;
                split_h16(v0, hh, ll); dth[d0] = hh;     dtl[d0] = ll;
                split_h16(v1, hh, ll); dth[d0 + 1] = hh; dtl[d0 + 1] = ll;
                split_h16(v2, hh, ll); dth[d1] = hh;     dtl[d1] = ll;
                split_h16(v3, hh, ll); dth[d1 + 1] = hh; dtl[d1 + 1] = ll;
            }
        }
    }
}

// ---------------------------------------------------------------------------
// fp32 -> fp16 hi/lo split (contiguous)
// ---------------------------------------------------------------------------
__global__ __launch_bounds__(256)
void split_kernel(const float* __restrict__ in, h16* __restrict__ oh,
                  h16* __restrict__ ol, int n)
{
    int i = (blockIdx.x * blockDim.x + threadIdx.x) * 4;
    if (i >= n) return;
    float4 v = *reinterpret_cast<const float4*>(in + i);
    h16 h0, l0, h1, l1, h2, l2, h3, l3;
    split_h16(v.x, h0, l0); split_h16(v.y, h1, l1);
    split_h16(v.z, h2, l2); split_h16(v.w, h3, l3);
    __half2* ph = reinterpret_cast<__half2*>(oh + i);
    __half2* pl = reinterpret_cast<__half2*>(ol + i);
    ph[0] = __half2(h0, h1); ph[1] = __half2(h2, h3);
    pl[0] = __half2(l0, l1); pl[1] = __half2(l2, l3);
}

// transpose + split:  in [R,C] fp32 -> out [C,R] fp16 hi (+lo if WRITELO)
template <bool WRITELO>
__global__ __launch_bounds__(256)
void tsplit_kernel(const float* __restrict__ in, h16* __restrict__ oh,
                   h16* __restrict__ ol, int R, int C)
{
    __shared__ float t[32][33];
    const int cx = blockIdx.x * 32, ry = blockIdx.y * 32;
    const int tx = threadIdx.x, ty = threadIdx.y;   // 32 x 8
    #pragma unroll
    for (int j = ty; j < 32; j += 8)
        t[j][tx] = in[(size_t)(ry + j) * C + cx + tx];
    __syncthreads();
    #pragma unroll
    for (int j = ty; j < 32; j += 8) {
        float v = t[tx][j];
        h16 h, l; split_h16(v, h, l);
        size_t o = (size_t)(cx + j) * R + ry + tx;
        oh[o] = h;
        if (WRITELO) ol[o] = l;
    }
}

// ---------------------------------------------------------------------------
// Depthwise conv (k=4, SAME: pad left 1, right 2) + SiLU, sliding window:
// each thread computes 4 consecutive l outputs (7 input loads instead of 16).
// COL0=0: x-half -> split fp16 (oh, ol). COL0=DHALF: z-half -> concat arrays
// (stride DINNER, offset DHALF).
// ---------------------------------------------------------------------------
template <int COL0, int OSTRIDE>
__global__ __launch_bounds__(256)
void conv_silu_kernel(const float* __restrict__ xz,
                      const float* __restrict__ w, const float* __restrict__ bias,
                      h16* __restrict__ oh, h16* __restrict__ ol)
{
    int idx = blockIdx.x * blockDim.x + threadIdx.x;   // < MROWS/4 * DHALF
    int c   = idx & (DHALF - 1);
    int bl4 = idx >> 10;                 // 0 .. MROWS/4-1
    int b   = bl4 >> 9;                  // LSEQ/4 = 512 groups per batch
    int l0  = (bl4 & 511) << 2;

    float w0 = w[c], w1 = w[DHALF + c], w2 = w[2 * DHALF + c], w3 = w[3 * DHALF + c];
    float bv = bias[c];

    const float* src = xz + ((size_t)b * LSEQ) * DINNER + COL0 + c;
    float win[7];
    #pragma unroll
    for (int j = 0; j < 7; j++) {
        int l = l0 + j - 1;
        win[j] = (l >= 0 && l < LSEQ) ? src[(size_t)l * DINNER] : 0.0f;
    }

    #pragma unroll
    for (int k = 0; k < 4; k++) {
        float acc = bv;
        acc = fmaf(win[k],     w0, acc);
        acc = fmaf(win[k + 1], w1, acc);
        acc = fmaf(win[k + 2], w2, acc);
        acc = fmaf(win[k + 3], w3, acc);
        float v = silu_f(acc);
        h16 h, lo; split_h16(v, h, lo);
        size_t o = ((size_t)b * LSEQ + l0 + k) * OSTRIDE + COL0 + c;
        oh[o] = h; ol[o] = lo;
    }
}

// ---------------------------------------------------------------------------
// Chunk-parallel selective scan.  A[d][n] = -(n+1) => dA_n = exp(-delta)^(n+1).
//   Phase 1: per (b, chunk, dblk) compute q and S = Sum(delta).   512 blocks
//   Phase 2: per (b, d) sequential combine over 16 chunks -> h_start.
//   Phase 3: replay each chunk from its h_start, emit y.          512 blocks
// u is reconstructed from the fp16 split pair (exact to 2^-22).
// ---------------------------------------------------------------------------
#define PW16(p1, pw)                                                    \
    float p2 = (p1) * (p1), p3 = p2 * (p1), p4 = p2 * p2;               \
    float p5 = p4 * (p1), p6 = p4 * p2, p7 = p4 * p3, p8 = p4 * p4;     \
    float pw[16] = {(p1), p2, p3, p4, p5, p6, p7, p8,                   \
                    p8 * (p1), p8 * p2, p8 * p3, p8 * p4,               \
                    p8 * p5, p8 * p6, p8 * p7, p8 * p8};

__global__ __launch_bounds__(128)
void scan_p1(const float* __restrict__ delta,
             const h16* __restrict__ uh, const h16* __restrict__ ul,
             const float* __restrict__ xdbl,
             float* __restrict__ q, float* __restrict__ S)
{
    const int tid = threadIdx.x;
    const int chunk = blockIdx.x, dblk = blockIdx.y, b = blockIdx.z;
    const int d = (dblk << 7) + tid;

    __shared__ float sB[16][DSTATE];
    __shared__ float sd[16][128];
    __shared__ float su[16][128];

    float h[DSTATE];
    #pragma unroll
    for (int n = 0; n < DSTATE; n++) h[n] = 0.0f;
    float sum = 0.0f;
    const size_t baseRow = (size_t)b * LSEQ + (size_t)chunk * LCHUNK;

    for (int t0 = 0; t0 < LCHUNK; t0 += 16) {
        {
            int s = tid >> 3;
            int i = (tid & 7) << 1;
            float2 v = *reinterpret_cast<const float2*>(
                xdbl + (baseRow + t0 + s) * XDBL_N + DTRANK + i);
            sB[s][i] = v.x; sB[s][i + 1] = v.y;
        }
        #pragma unroll
        for (int s = 0; s < 16; s++) {
            size_t r = (baseRow + t0 + s) * DHALF + d;
            sd[s][tid] = delta[r];
            su[s][tid] = __half2float(uh[r]) + __half2float(ul[r]);
        }
        __syncthreads();

        #pragma unroll
        for (int s = 0; s < 16; s++) {
            float dl = sd[s][tid];
            float du = dl * su[s][tid];
            sum += dl;
            float p1 = __expf(-dl);
            PW16(p1, pw)
            #pragma unroll
            for (int n = 0; n < DSTATE; n++)
                h[n] = fmaf(pw[n], h[n], du * sB[s][n]);
        }
        __syncthreads();
    }
    const size_t cbase = ((size_t)(b * NCHUNK + chunk) * DSTATE) * DHALF + d;
    #pragma unroll
    for (int n = 0; n < DSTATE; n++) q[cbase + (size_t)n * DHALF] = h[n];
    S[(size_t)(b * NCHUNK + chunk) * DHALF + d] = sum;
}

__global__ __launch_bounds__(128)
void scan_p2(const float* __restrict__ q, const float* __restrict__ S,
             float* __restrict__ hs)
{
    const int idx = blockIdx.x * 128 + threadIdx.x;   // < 4096
    const int b = idx >> 10, d = idx & (DHALF - 1);
    float h[DSTATE];
    #pragma unroll
    for (int n = 0; n < DSTATE; n++) h[n] = 0.0f;
    for (int c = 0; c < NCHUNK; c++) {
        const size_t cbase = ((size_t)(b * NCHUNK + c) * DSTATE) * DHALF + d;
        #pragma unroll
        for (int n = 0; n < DSTATE; n++) hs[cbase + (size_t)n * DHALF] = h[n];
        float s = S[(size_t)(b * NCHUNK + c) * DHALF + d];
        float p1 = __expf(-s);
        PW16(p1, pw)
        #pragma unroll
        for (int n = 0; n < DSTATE; n++)
            h[n] = fmaf(pw[n], h[n], q[cbase + (size_t)n * DHALF]);
    }
}

__global__ __launch_bounds__(128)
void scan_p3(const float* __restrict__ delta,
             const h16* __restrict__ uh, const h16* __restrict__ ul,
             const float* __restrict__ xdbl, const float* __restrict__ hs,
             const float* __restrict__ Dv,
             h16* __restrict__ cat_h, h16* __restrict__ cat_l)
{
    const int tid = threadIdx.x;
    const int chunk = blockIdx.x, dblk = blockIdx.y, b = blockIdx.z;
    const int d = (dblk << 7) + tid;

    __shared__ float sB[16][DSTATE];
    __shared__ float sC[16][DSTATE];
    __shared__ float sd[16][128];
    __shared__ float su[16][128];

    float h[DSTATE];
    const size_t cbase = ((size_t)(b * NCHUNK + chunk) * DSTATE) * DHALF + d;
    #pragma unroll
    for (int n = 0; n < DSTATE; n++) h[n] = hs[cbase + (size_t)n * DHALF];
    const float Dd = Dv[d];
    const size_t baseRow = (size_t)b * LSEQ + (size_t)chunk * LCHUNK;

    for (int t0 = 0; t0 < LCHUNK; t0 += 16) {
        {
            int s = tid >> 3;
            int i = (tid & 7) << 2;
            float4 v = *reinterpret_cast<const float4*>(
                xdbl + (baseRow + t0 + s) * XDBL_N + DTRANK + i);
            float vv[4] = {v.x, v.y, v.z, v.w};
            #pragma unroll
            for (int qq = 0; qq < 4; qq++) {
                int ii = i + qq;
                if (ii < DSTATE) sB[s][ii] = vv[qq];
                else             sC[s][ii - DSTATE] = vv[qq];
            }
        }
        #pragma unroll
        for (int s = 0; s < 16; s++) {
            size_t r = (baseRow + t0 + s) * DHALF + d;
            sd[s][tid] = delta[r];
            su[s][tid] = __half2float(uh[r]) + __half2float(ul[r]);
        }
        __syncthreads();

        #pragma unroll
        for (int s = 0; s < 16; s++) {
            float dl = sd[s][tid];
            float uu = su[s][tid];
            float du = dl * uu;
            float p1 = __expf(-dl);
            PW16(p1, pw)
            float y0 = 0.f, y1 = 0.f, y2 = 0.f, y3 = 0.f;
            #pragma unroll
            for (int n = 0; n < DSTATE; n += 4) {
                h[n + 0] = fmaf(pw[n + 0], h[n + 0], du * sB[s][n + 0]);
                h[n + 1] = fmaf(pw[n + 1], h[n + 1], du * sB[s][n + 1]);
                h[n + 2] = fmaf(pw[n + 2], h[n + 2], du * sB[s][n + 2]);
                h[n + 3] = fmaf(pw[n + 3], h[n + 3], du * sB[s][n + 3]);
                y0 = fmaf(h[n + 0], sC[s][n + 0], y0);
                y1 = fmaf(h[n + 1], sC[s][n + 1], y1);
                y2 = fmaf(h[n + 2], sC[s][n + 2], y2);
                y3 = fmaf(h[n + 3], sC[s][n + 3], y3);
            }
            float yv = fmaf(uu, Dd, (y0 + y1) + (y2 + y3));
            h16 hh, ll; split_h16(yv, hh, ll);
            size_t o = (baseRow + t0 + s) * DINNER + d;
            cat_h[o] = hh; cat_l[o] = ll;
        }
        __syncthreads();
    }
}

// ---------------------------------------------------------------------------
// Launch
// ---------------------------------------------------------------------------
extern "C" void kernel_launch(void* const* d_in, const int* in_sizes, int n_in,
                              void* d_out, int out_size)
{
    const float* x        = (const float*)d_in[0];
    const float* W_in     = (const float*)d_in[1];
    const float* conv_x_w = (const float*)d_in[2];
    const float* conv_x_b = (const float*)d_in[3];
    const float* conv_z_w = (const float*)d_in[4];
    const float* conv_z_b = (const float*)d_in[5];
    const float* W_xdbl   = (const float*)d_in[6];
    const float* W_dt     = (const float*)d_in[7];
    const float* inv_dt   = (const float*)d_in[8];
    const float* Dvec     = (const float*)d_in[9];
    const float* W_out    = (const float*)d_in[10];
    const float* b_out    = (const float*)d_in[11];
    float* out            = (float*)d_out;

    float *p_xz, *p_xdbl, *p_delta, *p_q, *p_hs, *p_S;
    h16 *p_a1h, *p_a1l, *p_b1h, *p_xsh, *p_xsl, *p_bxh, *p_bxl;
    h16 *p_dth, *p_dtl, *p_bdh, *p_bdl, *p_ch, *p_cl, *p_b2h;
    cudaGetSymbolAddress((void**)&p_xz,    g_xz);
    cudaGetSymbolAddress((void**)&p_xdbl,  g_xdbl);
    cudaGetSymbolAddress((void**)&p_delta, g_delta);
    cudaGetSymbolAddress((void**)&p_q,  g_q);
    cudaGetSymbolAddress((void**)&p_hs, g_hs);
    cudaGetSymbolAddress((void**)&p_S,  g_S);
    cudaGetSymbolAddress((void**)&p_a1h, g_a1h); cudaGetSymbolAddress((void**)&p_a1l, g_a1l);
    cudaGetSymbolAddress((void**)&p_b1h, g_b1h);
    cudaGetSymbolAddress((void**)&p_xsh, g_xsh); cudaGetSymbolAddress((void**)&p_xsl, g_xsl);
    cudaGetSymbolAddress((void**)&p_bxh, g_bxh); cudaGetSymbolAddress((void**)&p_bxl, g_bxl);
    cudaGetSymbolAddress((void**)&p_dth, g_dth); cudaGetSymbolAddress((void**)&p_dtl, g_dtl);
    cudaGetSymbolAddress((void**)&p_bdh, g_bdh); cudaGetSymbolAddress((void**)&p_bdl, g_bdl);
    cudaGetSymbolAddress((void**)&p_ch,  g_ch);  cudaGetSymbolAddress((void**)&p_cl,  g_cl);
    cudaGetSymbolAddress((void**)&p_b2h, g_b2h);

    constexpr int SMEM_S2  = 2 * (2 * 128 * 128 + 128 * 128) + 1024;  // 99328
    constexpr int SMEM3_128 = 3 * (128 * 128 + 128 * 128) + 1024;     // 99328
    constexpr int SMEM3_64  = 3 * (64 * 128 + 128 * 128) + 1024;      // 74752
    cudaFuncSetAttribute((const void*)gemm_mma2<false,false>,
                         cudaFuncAttributeMaxDynamicSharedMemorySize, SMEM_S2);
    cudaFuncSetAttribute((const void*)gemm_mma2<false,true>,
                         cudaFuncAttributeMaxDynamicSharedMemorySize, SMEM_S2);
    cudaFuncSetAttribute((const void*)gemm_mma3<128,true,true,false,false>,
                         cudaFuncAttributeMaxDynamicSharedMemorySize, SMEM3_128);
    cudaFuncSetAttribute((const void*)gemm_mma3<64,false,false,true,true>,
                         cudaFuncAttributeMaxDynamicSharedMemorySize, SMEM3_64);

    // 1) weight transposes + splits (lo skipped where 2-stream GEMMs ignore it)
    tsplit_kernel<false><<<dim3(DINNER / 32, DMODEL / 32), dim3(32, 8)>>>(W_in,   p_b1h, nullptr, DMODEL, DINNER);
    tsplit_kernel<true ><<<dim3(XDBL_N / 32, DHALF / 32),  dim3(32, 8)>>>(W_xdbl, p_bxh, p_bxl, DHALF,  XDBL_N);
    tsplit_kernel<true ><<<dim3(DHALF / 32, DTRANK / 32),  dim3(32, 8)>>>(W_dt,   p_bdh, p_bdl, DTRANK, DHALF);
    tsplit_kernel<false><<<dim3(DMODEL / 32, DINNER / 32), dim3(32, 8)>>>(W_out,  p_b2h, nullptr, DINNER, DMODEL);

    // 2) split x
    split_kernel<<<(MROWS * DMODEL / 4) / 256, 256>>>(x, p_a1h, p_a1l, MROWS * DMODEL);

    // 3) xz = x @ W_in                              [8192,2048]  (2-stream shared-B)
    gemm_mma2<false,false><<<dim3(DINNER / 128, MROWS / 128), 256, SMEM_S2>>>(
        p_a1h, p_a1l, p_b1h, nullptr, 0.0f, p_xz, DINNER, DMODEL);

    // 4) depthwise convs + silu (sliding window, split fp16 outputs)
    conv_silu_kernel<0, DHALF><<<(MROWS / 4 * DHALF) / 256, 256>>>(
        p_xz, conv_x_w, conv_x_b, p_xsh, p_xsl);
    conv_silu_kernel<DHALF, DINNER><<<(MROWS / 4 * DHALF) / 256, 256>>>(
        p_xz, conv_z_w, conv_z_b, p_ch - DHALF + DHALF, p_cl - DHALF + DHALF);

    // 5) x_dbl = xs @ W_xdbl  [8192,96] (3-stream)
    gemm_mma3<64,false,false,true,true><<<dim3(1, MROWS / 64), 256, SMEM3_64>>>(
        p_xsh, p_xsl, p_bxh, p_bxl, nullptr, 0.0f, p_xdbl, XDBL_N, DHALF, XDBL_N,
        p_dth, p_dtl);

    // 6) delta = softplus(dt_low @ W_dt + 2*inv_dt) [8192,1024] (3-stream)
    gemm_mma3<128,true,true,false,false><<<dim3(DHALF / 128, MROWS / 128), 256, SMEM3_128>>>(
        p_dth, p_dtl, p_bdh, p_bdl, inv_dt, 2.0f, p_delta, DHALF, DTRANK, DHALF,
        nullptr, nullptr);

    // 7) chunk-parallel selective scan -> concat left half (split fp16)
    scan_p1<<<dim3(NCHUNK, 8, B_SZ), 128>>>(p_delta, p_xsh, p_xsl, p_xdbl, p_q, p_S);
    scan_p2<<<32, 128>>>(p_q, p_S, p_hs);
    scan_p3<<<dim3(NCHUNK, 8, B_SZ), 128>>>(p_delta, p_xsh, p_xsl, p_xdbl, p_hs, Dvec, p_ch, p_cl);

    // 8) out = [y|z] @ W_out + b_out                [8192,1024]  (2-stream shared-B)
    gemm_mma2<false,true><<<dim3(DMODEL / 128, MROWS / 128), 256, SMEM_S2>>>(
        p_ch, p_cl, p_b2h, b_out, 1.0f, out, DMODEL, DINNER);
}

// round 9
// speedup vs baseline: 1.5332x; 1.4550x over previous
#include <cuda_runtime.h>
#include <cuda_fp16.h>
#include <cstdint>
#include <cstddef>

// ---------------------------------------------------------------------------
// Problem constants (MambaVisionMixer, B=4, L=2048)
// ---------------------------------------------------------------------------
#define B_SZ    4
#define LSEQ    2048
#define DMODEL  1024
#define DINNER  2048
#define DHALF   1024
#define DSTATE  16
#define DTRANK  64
#define XDBL_N  96
#define MROWS   (B_SZ*LSEQ)   // 8192
#define NCHUNK  16
#define LCHUNK  (LSEQ/NCHUNK) // 128

typedef __half h16;

// ---------------------------------------------------------------------------
// Device scratch (static __device__ arrays — no allocations)
// ---------------------------------------------------------------------------
__device__ float g_xz   [(size_t)MROWS * DINNER];   // 64 MB
__device__ float g_xdbl [(size_t)MROWS * XDBL_N];   // 3 MB
__device__ float g_delta[(size_t)MROWS * DHALF];    // 32 MB

__device__ float g_q [(size_t)B_SZ * NCHUNK * DSTATE * DHALF];  // 4 MB
__device__ float g_hs[(size_t)B_SZ * NCHUNK * DSTATE * DHALF];  // 4 MB
__device__ float g_S [(size_t)B_SZ * NCHUNK * DHALF];           // 256 KB

__device__ h16 g_a1h[(size_t)MROWS * DMODEL];      // x (fp16 rn)
__device__ h16 g_b1h[(size_t)DINNER * DMODEL];     // W_in^T  [2048,1024]
__device__ h16 g_xsh[(size_t)MROWS * DHALF];       // xs hi
__device__ h16 g_xsl[(size_t)MROWS * DHALF];       // xs lo (clean path: xdbl)
__device__ h16 g_bxh[(size_t)XDBL_N * DHALF];      // W_xdbl^T [96,1024]
__device__ h16 g_bxl[(size_t)XDBL_N * DHALF];
__device__ h16 g_dth[(size_t)MROWS * DTRANK];      // dt_low hi [8192,64]
__device__ h16 g_dtl[(size_t)MROWS * DTRANK];
__device__ h16 g_bdh[(size_t)DHALF * DTRANK];      // W_dt^T [1024,64]
__device__ h16 g_bdl[(size_t)DHALF * DTRANK];
__device__ h16 g_ch [(size_t)MROWS * DINNER];      // [y|z] (fp16 rn) [8192,2048]
__device__ h16 g_b2h[(size_t)DMODEL * DINNER];     // W_out^T [1024,2048]

// ---------------------------------------------------------------------------
// Helpers (sm_80-era ISA only: compiles at compute_103 non-'a' target)
// ---------------------------------------------------------------------------
__device__ __forceinline__ uint32_t smem_u32(const void* p) {
    uint32_t r;
    asm("{ .reg .u64 t; cvta.to.shared.u64 t, %1; cvt.u32.u64 %0, t; }"
        : "=r"(r) : "l"(p));
    return r;
}

#define CP16(dst, src) \
    asm volatile("cp.async.cg.shared.global [%0], [%1], 16;" \
        :: "r"(dst), "l"(src) : "memory")
#define CP16Z(dst, src, sz) \
    asm volatile("cp.async.cg.shared.global [%0], [%1], 16, %2;" \
        :: "r"(dst), "l"(src), "r"(sz) : "memory")
#define CP_COMMIT() asm volatile("cp.async.commit_group;" ::: "memory")
#define CP_WAIT2()  asm volatile("cp.async.wait_group 2;" ::: "memory")

__device__ __forceinline__ void ldsm4(uint32_t* r, uint32_t addr) {
    asm volatile("ldmatrix.sync.aligned.m8n8.x4.shared.b16 {%0,%1,%2,%3}, [%4];"
        : "=r"(r[0]), "=r"(r[1]), "=r"(r[2]), "=r"(r[3]) : "r"(addr));
}

__device__ __forceinline__ void mma16816(float* d, const uint32_t* a,
                                         const uint32_t* b) {
    asm volatile(
        "mma.sync.aligned.m16n8k16.row.col.f32.f16.f16.f32 "
        "{%0,%1,%2,%3}, {%4,%5,%6,%7}, {%8,%9}, {%0,%1,%2,%3};"
        : "+f"(d[0]), "+f"(d[1]), "+f"(d[2]), "+f"(d[3])
        : "r"(a[0]), "r"(a[1]), "r"(a[2]), "r"(a[3]), "r"(b[0]), "r"(b[1]));
}

__device__ __forceinline__ float softplus_f(float x) {
    return fmaxf(x, 0.0f) + log1pf(expf(-fabsf(x)));
}
__device__ __forceinline__ float silu_f(float x) {
    return x / (1.0f + expf(-x));
}
__device__ __forceinline__ void split_h16(float v, h16& h, h16& l) {
    h = __float2half_rn(v);
    l = __float2half_rn(v - __half2float(h));
}

// ---------------------------------------------------------------------------
// Tensor-core GEMM (mma.sync fp16, fp32 accum), extended-K streams.
//   C[M,N] = A[M,K] @ B^T   (B stored [N,K] row-major)
//   NSTREAM==1: plain fp16 GEMM (Ahi, Bhi)       -> error ~ 2*2^-11 incoherent
//   NSTREAM==3: (Ahi,Bhi),(Ahi,Blo),(Alo,Bhi)    -> error ~ 2^-22
//   CTA BMx128, 8 warps (2x4), warp tile (BM/2)x32, BK=64,
//   3-stage cp.async pipeline (R6 scheme, two syncs per chunk).
//   Smem rows 128B; SW128 swizzle chunk c ^= row&7 -> conflict-free ldmatrix.
//   DTSPLIT: additionally write fp16 hi/lo of cols [0,64) to dth/dtl.
// ---------------------------------------------------------------------------
template <int BM, int NSTREAM, bool SOFTPLUS, bool HASBIAS, bool NCHK, bool DTSPLIT>
__global__ __launch_bounds__(256, 2)
void gemm_mma(const h16* __restrict__ Ahi, const h16* __restrict__ Alo,
              const h16* __restrict__ Bhi, const h16* __restrict__ Blo,
              const float* __restrict__ bias, float bias_scale,
              float* __restrict__ C, int N, int K, int Brows,
              h16* __restrict__ dth, h16* __restrict__ dtl)
{
    constexpr int MI     = BM / 32;
    constexpr int ABYTES = BM * 128;
    constexpr int STAGE  = ABYTES + 128 * 128;
    extern __shared__ char dsm[];
    const uint32_t base = (smem_u32(dsm) + 1023u) & ~1023u;

    const int tid    = threadIdx.x;
    const int rowBlk = blockIdx.y * BM;
    const int colBlk = blockIdx.x * 128;
    const int wid    = tid >> 5;
    const int lane   = tid & 31;
    const int warp_m = wid >> 2;
    const int warp_n = wid & 3;
    const int mat    = lane >> 3;
    const int rin    = lane & 7;

    const int KC     = K / 64;
    const int CHUNKS = NSTREAM * KC;

    uint32_t offA[MI][4], offB[2][4];
    #pragma unroll
    for (int mi = 0; mi < MI; mi++)
        #pragma unroll
        for (int j = 0; j < 4; j++) {
            int row = warp_m * (BM / 2) + mi * 16 + (mat & 1) * 8 + rin;
            int c   = 2 * j + (mat >> 1);
            offA[mi][j] = row * 128 + ((c ^ (row & 7)) << 4);
        }
    #pragma unroll
    for (int bi = 0; bi < 2; bi++)
        #pragma unroll
        for (int j = 0; j < 4; j++) {
            int row = warp_n * 32 + bi * 16 + (mat >> 1) * 8 + rin;
            int c   = 2 * j + (mat & 1);
            offB[bi][j] = ABYTES + row * 128 + ((c ^ (row & 7)) << 4);
        }

    float acc[MI][4][4];
    #pragma unroll
    for (int i = 0; i < MI; i++)
        #pragma unroll
        for (int j = 0; j < 4; j++)
            #pragma unroll
            for (int q = 0; q < 4; q++) acc[i][j][q] = 0.0f;

    auto load_stage = [&](int s, int c) {
        int stream = (NSTREAM == 1) ? 0 : ((c >= 2 * KC) ? 2 : ((c >= KC) ? 1 : 0));
        int k0 = (c - stream * KC) * 64;
        const h16* Ap = (NSTREAM == 1) ? Ahi : ((stream == 2) ? Alo : Ahi);
        const h16* Bp = (NSTREAM == 1) ? Bhi : ((stream == 1) ? Blo : Bhi);
        uint32_t as_ = base + s * STAGE;
        uint32_t bs_ = as_ + ABYTES;
        #pragma unroll
        for (int t = 0; t < BM / 32; t++) {
            int idx = tid + t * 256;
            int r = idx >> 3, cc = idx & 7;
            uint32_t dst = as_ + r * 128 + ((cc ^ (r & 7)) << 4);
            const char* src =
                (const char*)(Ap + (size_t)(rowBlk + r) * K + k0) + cc * 16;
            CP16(dst, src);
        }
        #pragma unroll
        for (int t = 0; t < 4; t++) {
            int idx = tid + t * 256;
            int r = idx >> 3, cc = idx & 7;
            uint32_t dst = bs_ + r * 128 + ((cc ^ (r & 7)) << 4);
            if (NCHK) {
                int br = colBlk + r;
                int ok = (br < Brows);
                const char* src =
                    (const char*)(Bp + (size_t)(ok ? br : 0) * K + k0) + cc * 16;
                CP16Z(dst, src, ok ? 16u : 0u);
            } else {
                const char* src =
                    (const char*)(Bp + (size_t)(colBlk + r) * K + k0) + cc * 16;
                CP16(dst, src);
            }
        }
    };

    #pragma unroll
    for (int s = 0; s < 3; s++) { load_stage(s, s); CP_COMMIT(); }

    int slot = 0;
    #pragma unroll 1
    for (int i = 0; i < CHUNKS; i++) {
        CP_WAIT2();
        __syncthreads();
        const uint32_t sb = base + slot * STAGE;
        #pragma unroll
        for (int j = 0; j < 4; j++) {
            uint32_t Af[MI][4];
            #pragma unroll
            for (int mi = 0; mi < MI; mi++) ldsm4(Af[mi], sb + offA[mi][j]);
            uint32_t Bf[4][2];
            #pragma unroll
            for (int bi = 0; bi < 2; bi++) {
                uint32_t r[4];
                ldsm4(r, sb + offB[bi][j]);
                Bf[bi * 2 + 0][0] = r[0]; Bf[bi * 2 + 0][1] = r[1];
                Bf[bi * 2 + 1][0] = r[2]; Bf[bi * 2 + 1][1] = r[3];
            }
            #pragma unroll
            for (int mi = 0; mi < MI; mi++)
                #pragma unroll
                for (int ni = 0; ni < 4; ni++)
                    mma16816(acc[mi][ni], Af[mi], Bf[ni]);
        }
        __syncthreads();
        if (i + 3 < CHUNKS) load_stage(slot, i + 3);
        CP_COMMIT();
        slot = (slot == 2) ? 0 : slot + 1;
    }

    // epilogue
    const int mrow = rowBlk + warp_m * (BM / 2) + (lane >> 2);
    const int ncol = colBlk + warp_n * 32 + (lane & 3) * 2;
    #pragma unroll
    for (int mi = 0; mi < MI; mi++) {
        #pragma unroll
        for (int ni = 0; ni < 4; ni++) {
            int n0 = ncol + ni * 8;
            if (NCHK && n0 >= Brows) continue;
            float v0 = acc[mi][ni][0], v1 = acc[mi][ni][1];
            float v2 = acc[mi][ni][2], v3 = acc[mi][ni][3];
            if (HASBIAS) {
                float b0 = bias_scale * __ldg(bias + n0);
                float b1 = bias_scale * __ldg(bias + n0 + 1);
                v0 += b0; v1 += b1; v2 += b0; v3 += b1;
            }
            if (SOFTPLUS) {
                v0 = softplus_f(v0); v1 = softplus_f(v1);
                v2 = softplus_f(v2); v3 = softplus_f(v3);
            }
            size_t r0 = (size_t)(mrow + mi * 16) * N + n0;
            size_t r1 = (size_t)(mrow + mi * 16 + 8) * N + n0;
            *reinterpret_cast<float2*>(C + r0) = make_float2(v0, v1);
            *reinterpret_cast<float2*>(C + r1) = make_float2(v2, v3);
            if (DTSPLIT && n0 < DTRANK) {
                h16 hh, ll;
                size_t d0 = (size_t)(mrow + mi * 16) * DTRANK + n0;
                size_t d1 = (size_t)(mrow + mi * 16 + 8) * DTRANK + n0;
                split_h16(v0, hh, ll); dth[d0] = hh;     dtl[d0] = ll;
                split_h16(v1, hh, ll); dth[d0 + 1] = hh; dtl[d0 + 1] = ll;
                split_h16(v2, hh, ll); dth[d1] = hh;     dtl[d1] = ll;
                split_h16(v3, hh, ll); dth[d1 + 1] = hh; dtl[d1 + 1] = ll;
            }
        }
    }
}

// ---------------------------------------------------------------------------
// fp32 -> fp16 (round-to-nearest), contiguous
// ---------------------------------------------------------------------------
__global__ __launch_bounds__(256)
void cvt_h16_kernel(const float* __restrict__ in, h16* __restrict__ oh, int n)
{
    int i = (blockIdx.x * blockDim.x + threadIdx.x) * 4;
    if (i >= n) return;
    float4 v = *reinterpret_cast<const float4*>(in + i);
    __half2* ph = reinterpret_cast<__half2*>(oh + i);
    ph[0] = __half2(__float2half_rn(v.x), __float2half_rn(v.y));
    ph[1] = __half2(__float2half_rn(v.z), __float2half_rn(v.w));
}

// transpose + split:  in [R,C] fp32 -> out [C,R] fp16 hi (+lo if WRITELO)
template <bool WRITELO>
__global__ __launch_bounds__(256)
void tsplit_kernel(const float* __restrict__ in, h16* __restrict__ oh,
                   h16* __restrict__ ol, int R, int C)
{
    __shared__ float t[32][33];
    const int cx = blockIdx.x * 32, ry = blockIdx.y * 32;
    const int tx = threadIdx.x, ty = threadIdx.y;   // 32 x 8
    #pragma unroll
    for (int j = ty; j < 32; j += 8)
        t[j][tx] = in[(size_t)(ry + j) * C + cx + tx];
    __syncthreads();
    #pragma unroll
    for (int j = ty; j < 32; j += 8) {
        float v = t[tx][j];
        h16 h, l; split_h16(v, h, l);
        size_t o = (size_t)(cx + j) * R + ry + tx;
        oh[o] = h;
        if (WRITELO) ol[o] = l;
    }
}

// ---------------------------------------------------------------------------
// Depthwise conv (k=4, SAME: pad left 1, right 2) + SiLU, sliding window:
// each thread computes 4 consecutive l outputs.
// WRITELO=1 (x-half): split fp16 (oh+ol, clean xdbl path).
// WRITELO=0 (z-half): fp16 rn only, into concat right half.
// ---------------------------------------------------------------------------
template <int COL0, int OSTRIDE, bool WRITELO>
__global__ __launch_bounds__(256)
void conv_silu_kernel(const float* __restrict__ xz,
                      const float* __restrict__ w, const float* __restrict__ bias,
                      h16* __restrict__ oh, h16* __restrict__ ol)
{
    int idx = blockIdx.x * blockDim.x + threadIdx.x;   // < MROWS/4 * DHALF
    int c   = idx & (DHALF - 1);
    int bl4 = idx >> 10;
    int b   = bl4 >> 9;
    int l0  = (bl4 & 511) << 2;

    float w0 = w[c], w1 = w[DHALF + c], w2 = w[2 * DHALF + c], w3 = w[3 * DHALF + c];
    float bv = bias[c];

    const float* src = xz + ((size_t)b * LSEQ) * DINNER + COL0 + c;
    float win[7];
    #pragma unroll
    for (int j = 0; j < 7; j++) {
        int l = l0 + j - 1;
        win[j] = (l >= 0 && l < LSEQ) ? src[(size_t)l * DINNER] : 0.0f;
    }

    #pragma unroll
    for (int k = 0; k < 4; k++) {
        float acc = bv;
        acc = fmaf(win[k],     w0, acc);
        acc = fmaf(win[k + 1], w1, acc);
        acc = fmaf(win[k + 2], w2, acc);
        acc = fmaf(win[k + 3], w3, acc);
        float v = silu_f(acc);
        size_t o = ((size_t)b * LSEQ + l0 + k) * OSTRIDE + COL0 + c;
        if (WRITELO) {
            h16 h, lo; split_h16(v, h, lo);
            oh[o] = h; ol[o] = lo;
        } else {
            oh[o] = __float2half_rn(v);
        }
    }
}

// ---------------------------------------------------------------------------
// Chunk-parallel selective scan.  A[d][n] = -(n+1) => dA_n = exp(-delta)^(n+1).
//   Phase 1: per (b, chunk, dblk) compute q and S = Sum(delta).   512 blocks
//   Phase 2: per (b, d) sequential combine over 16 chunks -> h_start.
//   Phase 3: replay each chunk from its h_start, emit y (fp16).   512 blocks
// u is reconstructed from the fp16 split pair (exact to 2^-22).
// ---------------------------------------------------------------------------
#define PW16(p1, pw)                                                    \
    float p2 = (p1) * (p1), p3 = p2 * (p1), p4 = p2 * p2;               \
    float p5 = p4 * (p1), p6 = p4 * p2, p7 = p4 * p3, p8 = p4 * p4;     \
    float pw[16] = {(p1), p2, p3, p4, p5, p6, p7, p8,                   \
                    p8 * (p1), p8 * p2, p8 * p3, p8 * p4,               \
                    p8 * p5, p8 * p6, p8 * p7, p8 * p8};

__global__ __launch_bounds__(128)
void scan_p1(const float* __restrict__ delta,
             const h16* __restrict__ uh, const h16* __restrict__ ul,
             const float* __restrict__ xdbl,
             float* __restrict__ q, float* __restrict__ S)
{
    const int tid = threadIdx.x;
    const int chunk = blockIdx.x, dblk = blockIdx.y, b = blockIdx.z;
    const int d = (dblk << 7) + tid;

    __shared__ float sB[16][DSTATE];
    __shared__ float sd[16][128];
    __shared__ float su[16][128];

    float h[DSTATE];
    #pragma unroll
    for (int n = 0; n < DSTATE; n++) h[n] = 0.0f;
    float sum = 0.0f;
    const size_t baseRow = (size_t)b * LSEQ + (size_t)chunk * LCHUNK;

    for (int t0 = 0; t0 < LCHUNK; t0 += 16) {
        {
            int s = tid >> 3;
            int i = (tid & 7) << 1;
            float2 v = *reinterpret_cast<const float2*>(
                xdbl + (baseRow + t0 + s) * XDBL_N + DTRANK + i);
            sB[s][i] = v.x; sB[s][i + 1] = v.y;
        }
        #pragma unroll
        for (int s = 0; s < 16; s++) {
            size_t r = (baseRow + t0 + s) * DHALF + d;
            sd[s][tid] = delta[r];
            su[s][tid] = __half2float(uh[r]) + __half2float(ul[r]);
        }
        __syncthreads();

        #pragma unroll
        for (int s = 0; s < 16; s++) {
            float dl = sd[s][tid];
            float du = dl * su[s][tid];
            sum += dl;
            float p1 = __expf(-dl);
            PW16(p1, pw)
            #pragma unroll
            for (int n = 0; n < DSTATE; n++)
                h[n] = fmaf(pw[n], h[n], du * sB[s][n]);
        }
        __syncthreads();
    }
    const size_t cbase = ((size_t)(b * NCHUNK + chunk) * DSTATE) * DHALF + d;
    #pragma unroll
    for (int n = 0; n < DSTATE; n++) q[cbase + (size_t)n * DHALF] = h[n];
    S[(size_t)(b * NCHUNK + chunk) * DHALF + d] = sum;
}

__global__ __launch_bounds__(128)
void scan_p2(const float* __restrict__ q, const float* __restrict__ S,
             float* __restrict__ hs)
{
    const int idx = blockIdx.x * 128 + threadIdx.x;   // < 4096
    const int b = idx >> 10, d = idx & (DHALF - 1);
    float h[DSTATE];
    #pragma unroll
    for (int n = 0; n < DSTATE; n++) h[n] = 0.0f;
    for (int c = 0; c < NCHUNK; c++) {
        const size_t cbase = ((size_t)(b * NCHUNK + c) * DSTATE) * DHALF + d;
        #pragma unroll
        for (int n = 0; n < DSTATE; n++) hs[cbase + (size_t)n * DHALF] = h[n];
        float s = S[(size_t)(b * NCHUNK + c) * DHALF + d];
        float p1 = __expf(-s);
        PW16(p1, pw)
        #pragma unroll
        for (int n = 0; n < DSTATE; n++)
            h[n] = fmaf(pw[n], h[n], q[cbase + (size_t)n * DHALF]);
    }
}

__global__ __launch_bounds__(128)
void scan_p3(const float* __restrict__ delta,
             const h16* __restrict__ uh, const h16* __restrict__ ul,
             const float* __restrict__ xdbl, const float* __restrict__ hs,
             const float* __restrict__ Dv,
             h16* __restrict__ cat_h)
{
    const int tid = threadIdx.x;
    const int chunk = blockIdx.x, dblk = blockIdx.y, b = blockIdx.z;
    const int d = (dblk << 7) + tid;

    __shared__ float sB[16][DSTATE];
    __shared__ float sC[16][DSTATE];
    __shared__ float sd[16][128];
    __shared__ float su[16][128];

    float h[DSTATE];
    const size_t cbase = ((size_t)(b * NCHUNK + chunk) * DSTATE) * DHALF + d;
    #pragma unroll
    for (int n = 0; n < DSTATE; n++) h[n] = hs[cbase + (size_t)n * DHALF];
    const float Dd = Dv[d];
    const size_t baseRow = (size_t)b * LSEQ + (size_t)chunk * LCHUNK;

    for (int t0 = 0; t0 < LCHUNK; t0 += 16) {
        {
            int s = tid >> 3;
            int i = (tid & 7) << 2;
            float4 v = *reinterpret_cast<const float4*>(
                xdbl + (baseRow + t0 + s) * XDBL_N + DTRANK + i);
            float vv[4] = {v.x, v.y, v.z, v.w};
            #pragma unroll
            for (int qq = 0; qq < 4; qq++) {
                int ii = i + qq;
                if (ii < DSTATE) sB[s][ii] = vv[qq];
                else             sC[s][ii - DSTATE] = vv[qq];
            }
        }
        #pragma unroll
        for (int s = 0; s < 16; s++) {
            size_t r = (baseRow + t0 + s) * DHALF + d;
            sd[s][tid] = delta[r];
            su[s][tid] = __half2float(uh[r]) + __half2float(ul[r]);
        }
        __syncthreads();

        #pragma unroll
        for (int s = 0; s < 16; s++) {
            float dl = sd[s][tid];
            float uu = su[s][tid];
            float du = dl * uu;
            float p1 = __expf(-dl);
            PW16(p1, pw)
            float y0 = 0.f, y1 = 0.f, y2 = 0.f, y3 = 0.f;
            #pragma unroll
            for (int n = 0; n < DSTATE; n += 4) {
                h[n + 0] = fmaf(pw[n + 0], h[n + 0], du * sB[s][n + 0]);
                h[n + 1] = fmaf(pw[n + 1], h[n + 1], du * sB[s][n + 1]);
                h[n + 2] = fmaf(pw[n + 2], h[n + 2], du * sB[s][n + 2]);
                h[n + 3] = fmaf(pw[n + 3], h[n + 3], du * sB[s][n + 3]);
                y0 = fmaf(h[n + 0], sC[s][n + 0], y0);
                y1 = fmaf(h[n + 1], sC[s][n + 1], y1);
                y2 = fmaf(h[n + 2], sC[s][n + 2], y2);
                y3 = fmaf(h[n + 3], sC[s][n + 3], y3);
            }
            float yv = fmaf(uu, Dd, (y0 + y1) + (y2 + y3));
            cat_h[(baseRow + t0 + s) * DINNER + d] = __float2half_rn(yv);
        }
        __syncthreads();
    }
}

// ---------------------------------------------------------------------------
// Launch
// ---------------------------------------------------------------------------
extern "C" void kernel_launch(void* const* d_in, const int* in_sizes, int n_in,
                              void* d_out, int out_size)
{
    const float* x        = (const float*)d_in[0];
    const float* W_in     = (const float*)d_in[1];
    const float* conv_x_w = (const float*)d_in[2];
    const float* conv_x_b = (const float*)d_in[3];
    const float* conv_z_w = (const float*)d_in[4];
    const float* conv_z_b = (const float*)d_in[5];
    const float* W_xdbl   = (const float*)d_in[6];
    const float* W_dt     = (const float*)d_in[7];
    const float* inv_dt   = (const float*)d_in[8];
    const float* Dvec     = (const float*)d_in[9];
    const float* W_out    = (const float*)d_in[10];
    const float* b_out    = (const float*)d_in[11];
    float* out            = (float*)d_out;

    float *p_xz, *p_xdbl, *p_delta, *p_q, *p_hs, *p_S;
    h16 *p_a1h, *p_b1h, *p_xsh, *p_xsl, *p_bxh, *p_bxl;
    h16 *p_dth, *p_dtl, *p_bdh, *p_bdl, *p_ch, *p_b2h;
    cudaGetSymbolAddress((void**)&p_xz,    g_xz);
    cudaGetSymbolAddress((void**)&p_xdbl,  g_xdbl);
    cudaGetSymbolAddress((void**)&p_delta, g_delta);
    cudaGetSymbolAddress((void**)&p_q,  g_q);
    cudaGetSymbolAddress((void**)&p_hs, g_hs);
    cudaGetSymbolAddress((void**)&p_S,  g_S);
    cudaGetSymbolAddress((void**)&p_a1h, g_a1h);
    cudaGetSymbolAddress((void**)&p_b1h, g_b1h);
    cudaGetSymbolAddress((void**)&p_xsh, g_xsh); cudaGetSymbolAddress((void**)&p_xsl, g_xsl);
    cudaGetSymbolAddress((void**)&p_bxh, g_bxh); cudaGetSymbolAddress((void**)&p_bxl, g_bxl);
    cudaGetSymbolAddress((void**)&p_dth, g_dth); cudaGetSymbolAddress((void**)&p_dtl, g_dtl);
    cudaGetSymbolAddress((void**)&p_bdh, g_bdh); cudaGetSymbolAddress((void**)&p_bdl, g_bdl);
    cudaGetSymbolAddress((void**)&p_ch,  g_ch);
    cudaGetSymbolAddress((void**)&p_b2h, g_b2h);

    constexpr int SMEM_128 = 3 * (128 * 128 + 128 * 128) + 1024;   // 99328
    constexpr int SMEM_64  = 3 * (64 * 128 + 128 * 128) + 1024;    // 74752
    cudaFuncSetAttribute((const void*)gemm_mma<128,1,false,false,false,false>,
                         cudaFuncAttributeMaxDynamicSharedMemorySize, SMEM_128);
    cudaFuncSetAttribute((const void*)gemm_mma<128,1,false,true,false,false>,
                         cudaFuncAttributeMaxDynamicSharedMemorySize, SMEM_128);
    cudaFuncSetAttribute((const void*)gemm_mma<128,3,true,true,false,false>,
                         cudaFuncAttributeMaxDynamicSharedMemorySize, SMEM_128);
    cudaFuncSetAttribute((const void*)gemm_mma<64,3,false,false,true,true>,
                         cudaFuncAttributeMaxDynamicSharedMemorySize, SMEM_64);

    // 1) weight transposes (+splits only where 3-stream GEMMs need lo)
    tsplit_kernel<false><<<dim3(DINNER / 32, DMODEL / 32), dim3(32, 8)>>>(W_in,   p_b1h, nullptr, DMODEL, DINNER);
    tsplit_kernel<true ><<<dim3(XDBL_N / 32, DHALF / 32),  dim3(32, 8)>>>(W_xdbl, p_bxh, p_bxl, DHALF,  XDBL_N);
    tsplit_kernel<true ><<<dim3(DHALF / 32, DTRANK / 32),  dim3(32, 8)>>>(W_dt,   p_bdh, p_bdl, DTRANK, DHALF);
    tsplit_kernel<false><<<dim3(DMODEL / 32, DINNER / 32), dim3(32, 8)>>>(W_out,  p_b2h, nullptr, DINNER, DMODEL);

    // 2) x -> fp16 (rn)
    cvt_h16_kernel<<<(MROWS * DMODEL / 4) / 256, 256>>>(x, p_a1h, MROWS * DMODEL);

    // 3) xz = x @ W_in                              [8192,2048]  (1-stream)
    gemm_mma<128,1,false,false,false,false><<<dim3(DINNER / 128, MROWS / 128), 256, SMEM_128>>>(
        p_a1h, nullptr, p_b1h, nullptr, nullptr, 0.0f, p_xz, DINNER, DMODEL, DINNER,
        nullptr, nullptr);

    // 4) depthwise convs + silu (x-half split for clean xdbl path; z-half rn)
    conv_silu_kernel<0, DHALF, true><<<(MROWS / 4 * DHALF) / 256, 256>>>(
        p_xz, conv_x_w, conv_x_b, p_xsh, p_xsl);
    conv_silu_kernel<DHALF, DINNER, false><<<(MROWS / 4 * DHALF) / 256, 256>>>(
        p_xz, conv_z_w, conv_z_b, p_ch, nullptr);

    // 5) x_dbl = xs @ W_xdbl  [8192,96] (3-stream; feeds B/C/dt — keep clean)
    gemm_mma<64,3,false,false,true,true><<<dim3(1, MROWS / 64), 256, SMEM_64>>>(
        p_xsh, p_xsl, p_bxh, p_bxl, nullptr, 0.0f, p_xdbl, XDBL_N, DHALF, XDBL_N,
        p_dth, p_dtl);

    // 6) delta = softplus(dt_low @ W_dt + 2*inv_dt) [8192,1024] (3-stream)
    gemm_mma<128,3,true,true,false,false><<<dim3(DHALF / 128, MROWS / 128), 256, SMEM_128>>>(
        p_dth, p_dtl, p_bdh, p_bdl, inv_dt, 2.0f, p_delta, DHALF, DTRANK, DHALF,
        nullptr, nullptr);

    // 7) chunk-parallel selective scan -> concat left half (fp16 rn)
    scan_p1<<<dim3(NCHUNK, 8, B_SZ), 128>>>(p_delta, p_xsh, p_xsl, p_xdbl, p_q, p_S);
    scan_p2<<<32, 128>>>(p_q, p_S, p_hs);
    scan_p3<<<dim3(NCHUNK, 8, B_SZ), 128>>>(p_delta, p_xsh, p_xsl, p_xdbl, p_hs, Dvec, p_ch);

    // 8) out = [y|z] @ W_out + b_out                [8192,1024]  (1-stream)
    gemm_mma<128,1,false,true,false,false><<<dim3(DMODEL / 128, MROWS / 128), 256, SMEM_128>>>(
        p_ch, nullptr, p_b2h, nullptr, b_out, 1.0f, out, DMODEL, DINNER, DMODEL,
        nullptr, nullptr);
}

// round 10
// speedup vs baseline: 1.5738x; 1.0265x over previous
#include <cuda_runtime.h>
#include <cuda_fp16.h>
#include <cstdint>
#include <cstddef>

// ---------------------------------------------------------------------------
// Problem constants (MambaVisionMixer, B=4, L=2048)
// ---------------------------------------------------------------------------
#define B_SZ    4
#define LSEQ    2048
#define DMODEL  1024
#define DINNER  2048
#define DHALF   1024
#define DSTATE  16
#define DTRANK  64
#define XDBL_N  96
#define MROWS   (B_SZ*LSEQ)   // 8192
#define NCHUNK  16
#define LCHUNK  (LSEQ/NCHUNK) // 128

typedef __half h16;

// ---------------------------------------------------------------------------
// Device scratch (static __device__ arrays — no allocations)
// ---------------------------------------------------------------------------
__device__ h16   g_xzh [(size_t)MROWS * DINNER];    // xz fp16  (32 MB)
__device__ float g_xdbl [(size_t)MROWS * XDBL_N];   // 3 MB
__device__ float g_delta[(size_t)MROWS * DHALF];    // 32 MB

__device__ float g_q [(size_t)B_SZ * NCHUNK * DSTATE * DHALF];  // 4 MB
__device__ float g_hs[(size_t)B_SZ * NCHUNK * DSTATE * DHALF];  // 4 MB
__device__ float g_S [(size_t)B_SZ * NCHUNK * DHALF];           // 256 KB

__device__ h16 g_a1h[(size_t)MROWS * DMODEL];      // x (fp16 rn)
__device__ h16 g_b1h[(size_t)DINNER * DMODEL];     // W_in^T  [2048,1024]
__device__ h16 g_xsh[(size_t)MROWS * DHALF];       // xs hi
__device__ h16 g_xsl[(size_t)MROWS * DHALF];       // xs lo
__device__ h16 g_bxh[(size_t)XDBL_N * DHALF];      // W_xdbl^T [96,1024]
__device__ h16 g_dth[(size_t)MROWS * DTRANK];      // dt_low hi [8192,64]
__device__ h16 g_dtl[(size_t)MROWS * DTRANK];
__device__ h16 g_bdh[(size_t)DHALF * DTRANK];      // W_dt^T [1024,64]
__device__ h16 g_bdl[(size_t)DHALF * DTRANK];
__device__ h16 g_ch [(size_t)MROWS * DINNER];      // [y|z] (fp16 rn) [8192,2048]
__device__ h16 g_b2h[(size_t)DMODEL * DINNER];     // W_out^T [1024,2048]

// ---------------------------------------------------------------------------
// Helpers (sm_80-era ISA only: compiles at compute_103 non-'a' target)
// ---------------------------------------------------------------------------
__device__ __forceinline__ uint32_t smem_u32(const void* p) {
    uint32_t r;
    asm("{ .reg .u64 t; cvta.to.shared.u64 t, %1; cvt.u32.u64 %0, t; }"
        : "=r"(r) : "l"(p));
    return r;
}

#define CP16(dst, src) \
    asm volatile("cp.async.cg.shared.global [%0], [%1], 16;" \
        :: "r"(dst), "l"(src) : "memory")
#define CP16Z(dst, src, sz) \
    asm volatile("cp.async.cg.shared.global [%0], [%1], 16, %2;" \
        :: "r"(dst), "l"(src), "r"(sz) : "memory")
#define CP_COMMIT() asm volatile("cp.async.commit_group;" ::: "memory")
#define CP_WAIT2()  asm volatile("cp.async.wait_group 2;" ::: "memory")

__device__ __forceinline__ void ldsm4(uint32_t* r, uint32_t addr) {
    asm volatile("ldmatrix.sync.aligned.m8n8.x4.shared.b16 {%0,%1,%2,%3}, [%4];"
        : "=r"(r[0]), "=r"(r[1]), "=r"(r[2]), "=r"(r[3]) : "r"(addr));
}

__device__ __forceinline__ void mma16816(float* d, const uint32_t* a,
                                         const uint32_t* b) {
    asm volatile(
        "mma.sync.aligned.m16n8k16.row.col.f32.f16.f16.f32 "
        "{%0,%1,%2,%3}, {%4,%5,%6,%7}, {%8,%9}, {%0,%1,%2,%3};"
        : "+f"(d[0]), "+f"(d[1]), "+f"(d[2]), "+f"(d[3])
        : "r"(a[0]), "r"(a[1]), "r"(a[2]), "r"(a[3]), "r"(b[0]), "r"(b[1]));
}

__device__ __forceinline__ float softplus_f(float x) {
    return fmaxf(x, 0.0f) + log1pf(expf(-fabsf(x)));
}
__device__ __forceinline__ float silu_f(float x) {
    return x / (1.0f + expf(-x));
}
__device__ __forceinline__ void split_h16(float v, h16& h, h16& l) {
    h = __float2half_rn(v);
    l = __float2half_rn(v - __half2float(h));
}

// ---------------------------------------------------------------------------
// Tensor-core GEMM (mma.sync fp16, fp32 accum), extended-K streams.
//   C[M,N] = A[M,K] @ B^T   (B stored [N,K] row-major)
//   NSTREAM==1: (Ahi,Bhi)
//   NSTREAM==2: (Ahi,Bhi), (Alo,Bhi)          [drops A*Blo, err ~2^-12]
//   NSTREAM==3: (Ahi,Bhi), (Ahi,Blo), (Alo,Bhi)  [err ~2^-22]
//   CTA BMx128, 8 warps (2x4), warp tile (BM/2)x32, BK=64,
//   3-stage cp.async pipeline.  H16OUT: write C as fp16 rn.
//   DTSPLIT: additionally write fp16 hi/lo of cols [0,64) to dth/dtl.
// ---------------------------------------------------------------------------
template <int BM, int NSTREAM, bool SOFTPLUS, bool HASBIAS, bool NCHK,
          bool DTSPLIT, bool H16OUT>
__global__ __launch_bounds__(256, 2)
void gemm_mma(const h16* __restrict__ Ahi, const h16* __restrict__ Alo,
              const h16* __restrict__ Bhi, const h16* __restrict__ Blo,
              const float* __restrict__ bias, float bias_scale,
              void* __restrict__ Cout, int N, int K, int Brows,
              h16* __restrict__ dth, h16* __restrict__ dtl)
{
    constexpr int MI     = BM / 32;
    constexpr int ABYTES = BM * 128;
    constexpr int STAGE  = ABYTES + 128 * 128;
    extern __shared__ char dsm[];
    const uint32_t base = (smem_u32(dsm) + 1023u) & ~1023u;

    const int tid    = threadIdx.x;
    const int rowBlk = blockIdx.y * BM;
    const int colBlk = blockIdx.x * 128;
    const int wid    = tid >> 5;
    const int lane   = tid & 31;
    const int warp_m = wid >> 2;
    const int warp_n = wid & 3;
    const int mat    = lane >> 3;
    const int rin    = lane & 7;

    const int KC     = K / 64;
    const int CHUNKS = NSTREAM * KC;

    uint32_t offA[MI][4], offB[2][4];
    #pragma unroll
    for (int mi = 0; mi < MI; mi++)
        #pragma unroll
        for (int j = 0; j < 4; j++) {
            int row = warp_m * (BM / 2) + mi * 16 + (mat & 1) * 8 + rin;
            int c   = 2 * j + (mat >> 1);
            offA[mi][j] = row * 128 + ((c ^ (row & 7)) << 4);
        }
    #pragma unroll
    for (int bi = 0; bi < 2; bi++)
        #pragma unroll
        for (int j = 0; j < 4; j++) {
            int row = warp_n * 32 + bi * 16 + (mat >> 1) * 8 + rin;
            int c   = 2 * j + (mat & 1);
            offB[bi][j] = ABYTES + row * 128 + ((c ^ (row & 7)) << 4);
        }

    float acc[MI][4][4];
    #pragma unroll
    for (int i = 0; i < MI; i++)
        #pragma unroll
        for (int j = 0; j < 4; j++)
            #pragma unroll
            for (int q = 0; q < 4; q++) acc[i][j][q] = 0.0f;

    auto load_stage = [&](int s, int c) {
        int stream;
        if (NSTREAM == 1)      stream = 0;
        else if (NSTREAM == 2) stream = (c >= KC) ? 1 : 0;
        else                   stream = (c >= 2 * KC) ? 2 : ((c >= KC) ? 1 : 0);
        int k0 = (c - stream * KC) * 64;
        const h16* Ap = Ahi;
        const h16* Bp = Bhi;
        if (NSTREAM == 2) {
            if (stream == 1) Ap = Alo;
        } else if (NSTREAM == 3) {
            if (stream == 2) Ap = Alo;
            else if (stream == 1) Bp = Blo;
        }
        uint32_t as_ = base + s * STAGE;
        uint32_t bs_ = as_ + ABYTES;
        #pragma unroll
        for (int t = 0; t < BM / 32; t++) {
            int idx = tid + t * 256;
            int r = idx >> 3, cc = idx & 7;
            uint32_t dst = as_ + r * 128 + ((cc ^ (r & 7)) << 4);
            const char* src =
                (const char*)(Ap + (size_t)(rowBlk + r) * K + k0) + cc * 16;
            CP16(dst, src);
        }
        #pragma unroll
        for (int t = 0; t < 4; t++) {
            int idx = tid + t * 256;
            int r = idx >> 3, cc = idx & 7;
            uint32_t dst = bs_ + r * 128 + ((cc ^ (r & 7)) << 4);
            if (NCHK) {
                int br = colBlk + r;
                int ok = (br < Brows);
                const char* src =
                    (const char*)(Bp + (size_t)(ok ? br : 0) * K + k0) + cc * 16;
                CP16Z(dst, src, ok ? 16u : 0u);
            } else {
                const char* src =
                    (const char*)(Bp + (size_t)(colBlk + r) * K + k0) + cc * 16;
                CP16(dst, src);
            }
        }
    };

    #pragma unroll
    for (int s = 0; s < 3; s++) { load_stage(s, s); CP_COMMIT(); }

    int slot = 0;
    #pragma unroll 1
    for (int i = 0; i < CHUNKS; i++) {
        CP_WAIT2();
        __syncthreads();
        const uint32_t sb = base + slot * STAGE;
        #pragma unroll
        for (int j = 0; j < 4; j++) {
            uint32_t Af[MI][4];
            #pragma unroll
            for (int mi = 0; mi < MI; mi++) ldsm4(Af[mi], sb + offA[mi][j]);
            uint32_t Bf[4][2];
            #pragma unroll
            for (int bi = 0; bi < 2; bi++) {
                uint32_t r[4];
                ldsm4(r, sb + offB[bi][j]);
                Bf[bi * 2 + 0][0] = r[0]; Bf[bi * 2 + 0][1] = r[1];
                Bf[bi * 2 + 1][0] = r[2]; Bf[bi * 2 + 1][1] = r[3];
            }
            #pragma unroll
            for (int mi = 0; mi < MI; mi++)
                #pragma unroll
                for (int ni = 0; ni < 4; ni++)
                    mma16816(acc[mi][ni], Af[mi], Bf[ni]);
        }
        __syncthreads();
        if (i + 3 < CHUNKS) load_stage(slot, i + 3);
        CP_COMMIT();
        slot = (slot == 2) ? 0 : slot + 1;
    }

    // epilogue
    const int mrow = rowBlk + warp_m * (BM / 2) + (lane >> 2);
    const int ncol = colBlk + warp_n * 32 + (lane & 3) * 2;
    #pragma unroll
    for (int mi = 0; mi < MI; mi++) {
        #pragma unroll
        for (int ni = 0; ni < 4; ni++) {
            int n0 = ncol + ni * 8;
            if (NCHK && n0 >= Brows) continue;
            float v0 = acc[mi][ni][0], v1 = acc[mi][ni][1];
            float v2 = acc[mi][ni][2], v3 = acc[mi][ni][3];
            if (HASBIAS) {
                float b0 = bias_scale * __ldg(bias + n0);
                float b1 = bias_scale * __ldg(bias + n0 + 1);
                v0 += b0; v1 += b1; v2 += b0; v3 += b1;
            }
            if (SOFTPLUS) {
                v0 = softplus_f(v0); v1 = softplus_f(v1);
                v2 = softplus_f(v2); v3 = softplus_f(v3);
            }
            size_t r0 = (size_t)(mrow + mi * 16) * N + n0;
            size_t r1 = (size_t)(mrow + mi * 16 + 8) * N + n0;
            if (H16OUT) {
                h16* Ch = reinterpret_cast<h16*>(Cout);
                *reinterpret_cast<__half2*>(Ch + r0) =
                    __half2(__float2half_rn(v0), __float2half_rn(v1));
                *reinterpret_cast<__half2*>(Ch + r1) =
                    __half2(__float2half_rn(v2), __float2half_rn(v3));
            } else {
                float* Cf = reinterpret_cast<float*>(Cout);
                *reinterpret_cast<float2*>(Cf + r0) = make_float2(v0, v1);
                *reinterpret_cast<float2*>(Cf + r1) = make_float2(v2, v3);
            }
            if (DTSPLIT && n0 < DTRANK) {
                h16 hh, ll;
                size_t d0 = (size_t)(mrow + mi * 16) * DTRANK + n0;
                size_t d1 = (size_t)(mrow + mi * 16 + 8) * DTRANK + n0;
                split_h16(v0, hh, ll); dth[d0] = hh;     dtl[d0] = ll;
                split_h16(v1, hh, ll); dth[d0 + 1] = hh; dtl[d0 + 1] = ll;
                split_h16(v2, hh, ll); dth[d1] = hh;     dtl[d1] = ll;
                split_h16(v3, hh, ll); dth[d1 + 1] = hh; dtl[d1 + 1] = ll;
            }
        }
    }
}

// ---------------------------------------------------------------------------
// fp32 -> fp16 (round-to-nearest), contiguous
// ---------------------------------------------------------------------------
__global__ __launch_bounds__(256)
void cvt_h16_kernel(const float* __restrict__ in, h16* __restrict__ oh, int n)
{
    int i = (blockIdx.x * blockDim.x + threadIdx.x) * 4;
    if (i >= n) return;
    float4 v = *reinterpret_cast<const float4*>(in + i);
    __half2* ph = reinterpret_cast<__half2*>(oh + i);
    ph[0] = __half2(__float2half_rn(v.x), __float2half_rn(v.y));
    ph[1] = __half2(__float2half_rn(v.z), __float2half_rn(v.w));
}

// transpose + split:  in [R,C] fp32 -> out [C,R] fp16 hi (+lo if WRITELO)
template <bool WRITELO>
__global__ __launch_bounds__(256)
void tsplit_kernel(const float* __restrict__ in, h16* __restrict__ oh,
                   h16* __restrict__ ol, int R, int C)
{
    __shared__ float t[32][33];
    const int cx = blockIdx.x * 32, ry = blockIdx.y * 32;
    const int tx = threadIdx.x, ty = threadIdx.y;   // 32 x 8
    #pragma unroll
    for (int j = ty; j < 32; j += 8)
        t[j][tx] = in[(size_t)(ry + j) * C + cx + tx];
    __syncthreads();
    #pragma unroll
    for (int j = ty; j < 32; j += 8) {
        float v = t[tx][j];
        h16 h, l; split_h16(v, h, l);
        size_t o = (size_t)(cx + j) * R + ry + tx;
        oh[o] = h;
        if (WRITELO) ol[o] = l;
    }
}

// ---------------------------------------------------------------------------
// Depthwise conv (k=4, SAME: pad left 1, right 2) + SiLU over BOTH halves,
// sliding window (4 l-outputs per thread), fp16 xz input.
//   blockIdx.y == 0: x-half -> split fp16 (xsh + xsl)
//   blockIdx.y == 1: z-half -> fp16 rn into concat right half (stride DINNER)
// ---------------------------------------------------------------------------
__global__ __launch_bounds__(256)
void conv_both_kernel(const h16* __restrict__ xz,
                      const float* __restrict__ wx, const float* __restrict__ bx,
                      const float* __restrict__ wz, const float* __restrict__ bz,
                      h16* __restrict__ xsh, h16* __restrict__ xsl,
                      h16* __restrict__ ch)
{
    const int half = blockIdx.y;
    const float* w    = half ? wz : wx;
    const float* bias = half ? bz : bx;
    const int col0 = half ? DHALF : 0;

    int idx = blockIdx.x * blockDim.x + threadIdx.x;   // < MROWS/4 * DHALF
    int c   = idx & (DHALF - 1);
    int bl4 = idx >> 10;
    int b   = bl4 >> 9;
    int l0  = (bl4 & 511) << 2;

    float w0 = w[c], w1 = w[DHALF + c], w2 = w[2 * DHALF + c], w3 = w[3 * DHALF + c];
    float bv = bias[c];

    const h16* src = xz + ((size_t)b * LSEQ) * DINNER + col0 + c;
    float win[7];
    #pragma unroll
    for (int j = 0; j < 7; j++) {
        int l = l0 + j - 1;
        win[j] = (l >= 0 && l < LSEQ) ? __half2float(src[(size_t)l * DINNER]) : 0.0f;
    }

    #pragma unroll
    for (int k = 0; k < 4; k++) {
        float acc = bv;
        acc = fmaf(win[k],     w0, acc);
        acc = fmaf(win[k + 1], w1, acc);
        acc = fmaf(win[k + 2], w2, acc);
        acc = fmaf(win[k + 3], w3, acc);
        float v = silu_f(acc);
        size_t row = (size_t)b * LSEQ + l0 + k;
        if (half == 0) {
            h16 h, lo; split_h16(v, h, lo);
            size_t o = row * DHALF + c;
            xsh[o] = h; xsl[o] = lo;
        } else {
            ch[row * DINNER + DHALF + c] = __float2half_rn(v);
        }
    }
}

// ---------------------------------------------------------------------------
// Chunk-parallel selective scan.  A[d][n] = -(n+1) => dA_n = exp(-delta)^(n+1).
//   Phase 1: per (b, chunk, dblk) compute q and S = Sum(delta).   512 blocks
//   Phase 2: per (b, d) sequential combine over 16 chunks -> h_start.
//   Phase 3: replay each chunk from its h_start, emit y (fp16).   512 blocks
// u is reconstructed from the fp16 split pair (exact to 2^-22).
// ---------------------------------------------------------------------------
#define PW16(p1, pw)                                                    \
    float p2 = (p1) * (p1), p3 = p2 * (p1), p4 = p2 * p2;               \
    float p5 = p4 * (p1), p6 = p4 * p2, p7 = p4 * p3, p8 = p4 * p4;     \
    float pw[16] = {(p1), p2, p3, p4, p5, p6, p7, p8,                   \
                    p8 * (p1), p8 * p2, p8 * p3, p8 * p4,               \
                    p8 * p5, p8 * p6, p8 * p7, p8 * p8};

__global__ __launch_bounds__(128)
void scan_p1(const float* __restrict__ delta,
             const h16* __restrict__ uh, const h16* __restrict__ ul,
             const float* __restrict__ xdbl,
             float* __restrict__ q, float* __restrict__ S)
{
    const int tid = threadIdx.x;
    const int chunk = blockIdx.x, dblk = blockIdx.y, b = blockIdx.z;
    const int d = (dblk << 7) + tid;

    __shared__ float sB[16][DSTATE];
    __shared__ float sd[16][128];
    __shared__ float su[16][128];

    float h[DSTATE];
    #pragma unroll
    for (int n = 0; n < DSTATE; n++) h[n] = 0.0f;
    float sum = 0.0f;
    const size_t baseRow = (size_t)b * LSEQ + (size_t)chunk * LCHUNK;

    for (int t0 = 0; t0 < LCHUNK; t0 += 16) {
        {
            int s = tid >> 3;
            int i = (tid & 7) << 1;
            float2 v = *reinterpret_cast<const float2*>(
                xdbl + (baseRow + t0 + s) * XDBL_N + DTRANK + i);
            sB[s][i] = v.x; sB[s][i + 1] = v.y;
        }
        #pragma unroll
        for (int s = 0; s < 16; s++) {
            size_t r = (baseRow + t0 + s) * DHALF + d;
            sd[s][tid] = delta[r];
            su[s][tid] = __half2float(uh[r]) + __half2float(ul[r]);
        }
        __syncthreads();

        #pragma unroll
        for (int s = 0; s < 16; s++) {
            float dl = sd[s][tid];
            float du = dl * su[s][tid];
            sum += dl;
            float p1 = __expf(-dl);
            PW16(p1, pw)
            #pragma unroll
            for (int n = 0; n < DSTATE; n++)
                h[n] = fmaf(pw[n], h[n], du * sB[s][n]);
        }
        __syncthreads();
    }
    const size_t cbase = ((size_t)(b * NCHUNK + chunk) * DSTATE) * DHALF + d;
    #pragma unroll
    for (int n = 0; n < DSTATE; n++) q[cbase + (size_t)n * DHALF] = h[n];
    S[(size_t)(b * NCHUNK + chunk) * DHALF + d] = sum;
}

__global__ __launch_bounds__(128)
void scan_p2(const float* __restrict__ q, const float* __restrict__ S,
             float* __restrict__ hs)
{
    const int idx = blockIdx.x * 128 + threadIdx.x;   // < 4096
    const int b = idx >> 10, d = idx & (DHALF - 1);
    float h[DSTATE];
    #pragma unroll
    for (int n = 0; n < DSTATE; n++) h[n] = 0.0f;
    for (int c = 0; c < NCHUNK; c++) {
        const size_t cbase = ((size_t)(b * NCHUNK + c) * DSTATE) * DHALF + d;
        #pragma unroll
        for (int n = 0; n < DSTATE; n++) hs[cbase + (size_t)n * DHALF] = h[n];
        float s = S[(size_t)(b * NCHUNK + c) * DHALF + d];
        float p1 = __expf(-s);
        PW16(p1, pw)
        #pragma unroll
        for (int n = 0; n < DSTATE; n++)
            h[n] = fmaf(pw[n], h[n], q[cbase + (size_t)n * DHALF]);
    }
}

__global__ __launch_bounds__(128)
void scan_p3(const float* __restrict__ delta,
             const h16* __restrict__ uh, const h16* __restrict__ ul,
             const float* __restrict__ xdbl, const float* __restrict__ hs,
             const float* __restrict__ Dv,
             h16* __restrict__ cat_h)
{
    const int tid = threadIdx.x;
    const int chunk = blockIdx.x, dblk = blockIdx.y, b = blockIdx.z;
    const int d = (dblk << 7) + tid;

    __shared__ float sB[16][DSTATE];
    __shared__ float sC[16][DSTATE];
    __shared__ float sd[16][128];
    __shared__ float su[16][128];

    float h[DSTATE];
    const size_t cbase = ((size_t)(b * NCHUNK + chunk) * DSTATE) * DHALF + d;
    #pragma unroll
    for (int n = 0; n < DSTATE; n++) h[n] = hs[cbase + (size_t)n * DHALF];
    const float Dd = Dv[d];
    const size_t baseRow = (size_t)b * LSEQ + (size_t)chunk * LCHUNK;

    for (int t0 = 0; t0 < LCHUNK; t0 += 16) {
        {
            int s = tid >> 3;
            int i = (tid & 7) << 2;
            float4 v = *reinterpret_cast<const float4*>(
                xdbl + (baseRow + t0 + s) * XDBL_N + DTRANK + i);
            float vv[4] = {v.x, v.y, v.z, v.w};
            #pragma unroll
            for (int qq = 0; qq < 4; qq++) {
                int ii = i + qq;
                if (ii < DSTATE) sB[s][ii] = vv[qq];
                else             sC[s][ii - DSTATE] = vv[qq];
            }
        }
        #pragma unroll
        for (int s = 0; s < 16; s++) {
            size_t r = (baseRow + t0 + s) * DHALF + d;
            sd[s][tid] = delta[r];
            su[s][tid] = __half2float(uh[r]) + __half2float(ul[r]);
        }
        __syncthreads();

        #pragma unroll
        for (int s = 0; s < 16; s++) {
            float dl = sd[s][tid];
            float uu = su[s][tid];
            float du = dl * uu;
            float p1 = __expf(-dl);
            PW16(p1, pw)
            float y0 = 0.f, y1 = 0.f, y2 = 0.f, y3 = 0.f;
            #pragma unroll
            for (int n = 0; n < DSTATE; n += 4) {
                h[n + 0] = fmaf(pw[n + 0], h[n + 0], du * sB[s][n + 0]);
                h[n + 1] = fmaf(pw[n + 1], h[n + 1], du * sB[s][n + 1]);
                h[n + 2] = fmaf(pw[n + 2], h[n + 2], du * sB[s][n + 2]);
                h[n + 3] = fmaf(pw[n + 3], h[n + 3], du * sB[s][n + 3]);
                y0 = fmaf(h[n + 0], sC[s][n + 0], y0);
                y1 = fmaf(h[n + 1], sC[s][n + 1], y1);
                y2 = fmaf(h[n + 2], sC[s][n + 2], y2);
                y3 = fmaf(h[n + 3], sC[s][n + 3], y3);
            }
            float yv = fmaf(uu, Dd, (y0 + y1) + (y2 + y3));
            cat_h[(baseRow + t0 + s) * DINNER + d] = __float2half_rn(yv);
        }
        __syncthreads();
    }
}

// ---------------------------------------------------------------------------
// Launch
// ---------------------------------------------------------------------------
extern "C" void kernel_launch(void* const* d_in, const int* in_sizes, int n_in,
                              void* d_out, int out_size)
{
    const float* x        = (const float*)d_in[0];
    const float* W_in     = (const float*)d_in[1];
    const float* conv_x_w = (const float*)d_in[2];
    const float* conv_x_b = (const float*)d_in[3];
    const float* conv_z_w = (const float*)d_in[4];
    const float* conv_z_b = (const float*)d_in[5];
    const float* W_xdbl   = (const float*)d_in[6];
    const float* W_dt     = (const float*)d_in[7];
    const float* inv_dt   = (const float*)d_in[8];
    const float* Dvec     = (const float*)d_in[9];
    const float* W_out    = (const float*)d_in[10];
    const float* b_out    = (const float*)d_in[11];
    float* out            = (float*)d_out;

    float *p_xdbl, *p_delta, *p_q, *p_hs, *p_S;
    h16 *p_xzh, *p_a1h, *p_b1h, *p_xsh, *p_xsl, *p_bxh;
    h16 *p_dth, *p_dtl, *p_bdh, *p_bdl, *p_ch, *p_b2h;
    cudaGetSymbolAddress((void**)&p_xzh,   g_xzh);
    cudaGetSymbolAddress((void**)&p_xdbl,  g_xdbl);
    cudaGetSymbolAddress((void**)&p_delta, g_delta);
    cudaGetSymbolAddress((void**)&p_q,  g_q);
    cudaGetSymbolAddress((void**)&p_hs, g_hs);
    cudaGetSymbolAddress((void**)&p_S,  g_S);
    cudaGetSymbolAddress((void**)&p_a1h, g_a1h);
    cudaGetSymbolAddress((void**)&p_b1h, g_b1h);
    cudaGetSymbolAddress((void**)&p_xsh, g_xsh); cudaGetSymbolAddress((void**)&p_xsl, g_xsl);
    cudaGetSymbolAddress((void**)&p_bxh, g_bxh);
    cudaGetSymbolAddress((void**)&p_dth, g_dth); cudaGetSymbolAddress((void**)&p_dtl, g_dtl);
    cudaGetSymbolAddress((void**)&p_bdh, g_bdh); cudaGetSymbolAddress((void**)&p_bdl, g_bdl);
    cudaGetSymbolAddress((void**)&p_ch,  g_ch);
    cudaGetSymbolAddress((void**)&p_b2h, g_b2h);

    constexpr int SMEM_128 = 3 * (128 * 128 + 128 * 128) + 1024;   // 99328
    constexpr int SMEM_64  = 3 * (64 * 128 + 128 * 128) + 1024;    // 74752
    cudaFuncSetAttribute((const void*)gemm_mma<128,1,false,false,false,false,true>,
                         cudaFuncAttributeMaxDynamicSharedMemorySize, SMEM_128);
    cudaFuncSetAttribute((const void*)gemm_mma<128,1,false,true,false,false,false>,
                         cudaFuncAttributeMaxDynamicSharedMemorySize, SMEM_128);
    cudaFuncSetAttribute((const void*)gemm_mma<128,3,true,true,false,false,false>,
                         cudaFuncAttributeMaxDynamicSharedMemorySize, SMEM_128);
    cudaFuncSetAttribute((const void*)gemm_mma<64,2,false,false,true,true,false>,
                         cudaFuncAttributeMaxDynamicSharedMemorySize, SMEM_64);

    // 1) weight transposes (+splits only where needed)
    tsplit_kernel<false><<<dim3(DINNER / 32, DMODEL / 32), dim3(32, 8)>>>(W_in,   p_b1h, nullptr, DMODEL, DINNER);
    tsplit_kernel<false><<<dim3(XDBL_N / 32, DHALF / 32),  dim3(32, 8)>>>(W_xdbl, p_bxh, nullptr, DHALF,  XDBL_N);
    tsplit_kernel<true ><<<dim3(DHALF / 32, DTRANK / 32),  dim3(32, 8)>>>(W_dt,   p_bdh, p_bdl, DTRANK, DHALF);
    tsplit_kernel<false><<<dim3(DMODEL / 32, DINNER / 32), dim3(32, 8)>>>(W_out,  p_b2h, nullptr, DINNER, DMODEL);

    // 2) x -> fp16 (rn)
    cvt_h16_kernel<<<(MROWS * DMODEL / 4) / 256, 256>>>(x, p_a1h, MROWS * DMODEL);

    // 3) xz = x @ W_in                              [8192,2048]  (1-stream, fp16 out)
    gemm_mma<128,1,false,false,false,false,true><<<dim3(DINNER / 128, MROWS / 128), 256, SMEM_128>>>(
        p_a1h, nullptr, p_b1h, nullptr, nullptr, 0.0f, p_xzh, DINNER, DMODEL, DINNER,
        nullptr, nullptr);

    // 4) both depthwise convs + silu in one launch (fp16 xz input)
    conv_both_kernel<<<dim3((MROWS / 4 * DHALF) / 256, 2), 256>>>(
        p_xzh, conv_x_w, conv_x_b, conv_z_w, conv_z_b, p_xsh, p_xsl, p_ch);

    // 5) x_dbl = xs @ W_xdbl  [8192,96] (2-stream: (xs_hi+xs_lo) @ W_hi)
    gemm_mma<64,2,false,false,true,true,false><<<dim3(1, MROWS / 64), 256, SMEM_64>>>(
        p_xsh, p_xsl, p_bxh, nullptr, nullptr, 0.0f, p_xdbl, XDBL_N, DHALF, XDBL_N,
        p_dth, p_dtl);

    // 6) delta = softplus(dt_low @ W_dt + 2*inv_dt) [8192,1024] (3-stream)
    gemm_mma<128,3,true,true,false,false,false><<<dim3(DHALF / 128, MROWS / 128), 256, SMEM_128>>>(
        p_dth, p_dtl, p_bdh, p_bdl, inv_dt, 2.0f, p_delta, DHALF, DTRANK, DHALF,
        nullptr, nullptr);

    // 7) chunk-parallel selective scan -> concat left half (fp16 rn)
    scan_p1<<<dim3(NCHUNK, 8, B_SZ), 128>>>(p_delta, p_xsh, p_xsl, p_xdbl, p_q, p_S);
    scan_p2<<<32, 128>>>(p_q, p_S, p_hs);
    scan_p3<<<dim3(NCHUNK, 8, B_SZ), 128>>>(p_delta, p_xsh, p_xsl, p_xdbl, p_hs, Dvec, p_ch);

    // 8) out = [y|z] @ W_out + b_out                [8192,1024]  (1-stream)
    gemm_mma<128,1,false,true,false,false,false><<<dim3(DMODEL / 128, MROWS / 128), 256, SMEM_128>>>(
        p_ch, nullptr, p_b2h, nullptr, b_out, 1.0f, out, DMODEL, DINNER, DMODEL,
        nullptr, nullptr);
}

// round 11
// speedup vs baseline: 1.6255x; 1.0328x over previous
#include <cuda_runtime.h>
#include <cuda_fp16.h>
#include <cstdint>
#include <cstddef>

// ---------------------------------------------------------------------------
// Problem constants (MambaVisionMixer, B=4, L=2048)
// ---------------------------------------------------------------------------
#define B_SZ    4
#define LSEQ    2048
#define DMODEL  1024
#define DINNER  2048
#define DHALF   1024
#define DSTATE  16
#define DTRANK  64
#define XDBL_N  96
#define MROWS   (B_SZ*LSEQ)   // 8192
#define NCHUNK  32
#define LCHUNK  (LSEQ/NCHUNK) // 64

typedef __half h16;

// ---------------------------------------------------------------------------
// Device scratch (static __device__ arrays — no allocations)
// ---------------------------------------------------------------------------
__device__ h16   g_xzh [(size_t)MROWS * DINNER];    // xz fp16  (32 MB)
__device__ float g_xdbl [(size_t)MROWS * XDBL_N];   // 3 MB
__device__ float g_delta[(size_t)MROWS * DHALF];    // 32 MB

__device__ float g_q [(size_t)B_SZ * NCHUNK * DSTATE * DHALF];  // 8 MB
__device__ float g_hs[(size_t)B_SZ * NCHUNK * DSTATE * DHALF];  // 8 MB
__device__ float g_S [(size_t)B_SZ * NCHUNK * DHALF];           // 512 KB

__device__ h16 g_a1h[(size_t)MROWS * DMODEL];      // x (fp16 rn)
__device__ h16 g_b1h[(size_t)DINNER * DMODEL];     // W_in^T  [2048,1024]
__device__ h16 g_xsh[(size_t)MROWS * DHALF];       // xs hi
__device__ h16 g_xsl[(size_t)MROWS * DHALF];       // xs lo (xdbl path only)
__device__ h16 g_bxh[(size_t)XDBL_N * DHALF];      // W_xdbl^T [96,1024]
__device__ h16 g_dth[(size_t)MROWS * DTRANK];      // dt_low hi [8192,64]
__device__ h16 g_dtl[(size_t)MROWS * DTRANK];
__device__ h16 g_bdh[(size_t)DHALF * DTRANK];      // W_dt^T [1024,64]
__device__ h16 g_bdl[(size_t)DHALF * DTRANK];
__device__ h16 g_ch [(size_t)MROWS * DINNER];      // [y|z] (fp16 rn) [8192,2048]
__device__ h16 g_b2h[(size_t)DMODEL * DINNER];     // W_out^T [1024,2048]

// ---------------------------------------------------------------------------
// Helpers (sm_80-era ISA only: compiles at compute_103 non-'a' target)
// ---------------------------------------------------------------------------
__device__ __forceinline__ uint32_t smem_u32(const void* p) {
    uint32_t r;
    asm("{ .reg .u64 t; cvta.to.shared.u64 t, %1; cvt.u32.u64 %0, t; }"
        : "=r"(r) : "l"(p));
    return r;
}

#define CP16(dst, src) \
    asm volatile("cp.async.cg.shared.global [%0], [%1], 16;" \
        :: "r"(dst), "l"(src) : "memory")
#define CP16Z(dst, src, sz) \
    asm volatile("cp.async.cg.shared.global [%0], [%1], 16, %2;" \
        :: "r"(dst), "l"(src), "r"(sz) : "memory")
#define CP_COMMIT() asm volatile("cp.async.commit_group;" ::: "memory")
#define CP_WAIT2()  asm volatile("cp.async.wait_group 2;" ::: "memory")

__device__ __forceinline__ void ldsm4(uint32_t* r, uint32_t addr) {
    asm volatile("ldmatrix.sync.aligned.m8n8.x4.shared.b16 {%0,%1,%2,%3}, [%4];"
        : "=r"(r[0]), "=r"(r[1]), "=r"(r[2]), "=r"(r[3]) : "r"(addr));
}

__device__ __forceinline__ void mma16816(float* d, const uint32_t* a,
                                         const uint32_t* b) {
    asm volatile(
        "mma.sync.aligned.m16n8k16.row.col.f32.f16.f16.f32 "
        "{%0,%1,%2,%3}, {%4,%5,%6,%7}, {%8,%9}, {%0,%1,%2,%3};"
        : "+f"(d[0]), "+f"(d[1]), "+f"(d[2]), "+f"(d[3])
        : "r"(a[0]), "r"(a[1]), "r"(a[2]), "r"(a[3]), "r"(b[0]), "r"(b[1]));
}

__device__ __forceinline__ float softplus_f(float x) {
    return fmaxf(x, 0.0f) + log1pf(expf(-fabsf(x)));
}
__device__ __forceinline__ float silu_f(float x) {
    return x / (1.0f + expf(-x));
}
__device__ __forceinline__ void split_h16(float v, h16& h, h16& l) {
    h = __float2half_rn(v);
    l = __float2half_rn(v - __half2float(h));
}

// ---------------------------------------------------------------------------
// Tensor-core GEMM (mma.sync fp16, fp32 accum), extended-K streams.
//   C[M,N] = A[M,K] @ B^T   (B stored [N,K] row-major)
//   NSTREAM==1: (Ahi,Bhi)
//   NSTREAM==2: (Ahi,Bhi), (Alo,Bhi)
//   NSTREAM==3: (Ahi,Bhi), (Ahi,Blo), (Alo,Bhi)
//   CTA BMx128, 8 warps (2x4), warp tile (BM/2)x32, BK=64,
//   3-stage cp.async pipeline.  H16OUT: write C as fp16 rn.
//   DTSPLIT: additionally write fp16 hi/lo of cols [0,64) to dth/dtl.
// ---------------------------------------------------------------------------
template <int BM, int NSTREAM, bool SOFTPLUS, bool HASBIAS, bool NCHK,
          bool DTSPLIT, bool H16OUT>
__global__ __launch_bounds__(256, 2)
void gemm_mma(const h16* __restrict__ Ahi, const h16* __restrict__ Alo,
              const h16* __restrict__ Bhi, const h16* __restrict__ Blo,
              const float* __restrict__ bias, float bias_scale,
              void* __restrict__ Cout, int N, int K, int Brows,
              h16* __restrict__ dth, h16* __restrict__ dtl)
{
    constexpr int MI     = BM / 32;
    constexpr int ABYTES = BM * 128;
    constexpr int STAGE  = ABYTES + 128 * 128;
    extern __shared__ char dsm[];
    const uint32_t base = (smem_u32(dsm) + 1023u) & ~1023u;

    const int tid    = threadIdx.x;
    const int rowBlk = blockIdx.y * BM;
    const int colBlk = blockIdx.x * 128;
    const int wid    = tid >> 5;
    const int lane   = tid & 31;
    const int warp_m = wid >> 2;
    const int warp_n = wid & 3;
    const int mat    = lane >> 3;
    const int rin    = lane & 7;

    const int KC     = K / 64;
    const int CHUNKS = NSTREAM * KC;

    uint32_t offA[MI][4], offB[2][4];
    #pragma unroll
    for (int mi = 0; mi < MI; mi++)
        #pragma unroll
        for (int j = 0; j < 4; j++) {
            int row = warp_m * (BM / 2) + mi * 16 + (mat & 1) * 8 + rin;
            int c   = 2 * j + (mat >> 1);
            offA[mi][j] = row * 128 + ((c ^ (row & 7)) << 4);
        }
    #pragma unroll
    for (int bi = 0; bi < 2; bi++)
        #pragma unroll
        for (int j = 0; j < 4; j++) {
            int row = warp_n * 32 + bi * 16 + (mat >> 1) * 8 + rin;
            int c   = 2 * j + (mat & 1);
            offB[bi][j] = ABYTES + row * 128 + ((c ^ (row & 7)) << 4);
        }

    float acc[MI][4][4];
    #pragma unroll
    for (int i = 0; i < MI; i++)
        #pragma unroll
        for (int j = 0; j < 4; j++)
            #pragma unroll
            for (int q = 0; q < 4; q++) acc[i][j][q] = 0.0f;

    auto load_stage = [&](int s, int c) {
        int stream;
        if (NSTREAM == 1)      stream = 0;
        else if (NSTREAM == 2) stream = (c >= KC) ? 1 : 0;
        else                   stream = (c >= 2 * KC) ? 2 : ((c >= KC) ? 1 : 0);
        int k0 = (c - stream * KC) * 64;
        const h16* Ap = Ahi;
        const h16* Bp = Bhi;
        if (NSTREAM == 2) {
            if (stream == 1) Ap = Alo;
        } else if (NSTREAM == 3) {
            if (stream == 2) Ap = Alo;
            else if (stream == 1) Bp = Blo;
        }
        uint32_t as_ = base + s * STAGE;
        uint32_t bs_ = as_ + ABYTES;
        #pragma unroll
        for (int t = 0; t < BM / 32; t++) {
            int idx = tid + t * 256;
            int r = idx >> 3, cc = idx & 7;
            uint32_t dst = as_ + r * 128 + ((cc ^ (r & 7)) << 4);
            const char* src =
                (const char*)(Ap + (size_t)(rowBlk + r) * K + k0) + cc * 16;
            CP16(dst, src);
        }
        #pragma unroll
        for (int t = 0; t < 4; t++) {
            int idx = tid + t * 256;
            int r = idx >> 3, cc = idx & 7;
            uint32_t dst = bs_ + r * 128 + ((cc ^ (r & 7)) << 4);
            if (NCHK) {
                int br = colBlk + r;
                int ok = (br < Brows);
                const char* src =
                    (const char*)(Bp + (size_t)(ok ? br : 0) * K + k0) + cc * 16;
                CP16Z(dst, src, ok ? 16u : 0u);
            } else {
                const char* src =
                    (const char*)(Bp + (size_t)(colBlk + r) * K + k0) + cc * 16;
                CP16(dst, src);
            }
        }
    };

    #pragma unroll
    for (int s = 0; s < 3; s++) { load_stage(s, s); CP_COMMIT(); }

    int slot = 0;
    #pragma unroll 1
    for (int i = 0; i < CHUNKS; i++) {
        CP_WAIT2();
        __syncthreads();
        const uint32_t sb = base + slot * STAGE;
        #pragma unroll
        for (int j = 0; j < 4; j++) {
            uint32_t Af[MI][4];
            #pragma unroll
            for (int mi = 0; mi < MI; mi++) ldsm4(Af[mi], sb + offA[mi][j]);
            uint32_t Bf[4][2];
            #pragma unroll
            for (int bi = 0; bi < 2; bi++) {
                uint32_t r[4];
                ldsm4(r, sb + offB[bi][j]);
                Bf[bi * 2 + 0][0] = r[0]; Bf[bi * 2 + 0][1] = r[1];
                Bf[bi * 2 + 1][0] = r[2]; Bf[bi * 2 + 1][1] = r[3];
            }
            #pragma unroll
            for (int mi = 0; mi < MI; mi++)
                #pragma unroll
                for (int ni = 0; ni < 4; ni++)
                    mma16816(acc[mi][ni], Af[mi], Bf[ni]);
        }
        __syncthreads();
        if (i + 3 < CHUNKS) load_stage(slot, i + 3);
        CP_COMMIT();
        slot = (slot == 2) ? 0 : slot + 1;
    }

    // epilogue
    const int mrow = rowBlk + warp_m * (BM / 2) + (lane >> 2);
    const int ncol = colBlk + warp_n * 32 + (lane & 3) * 2;
    #pragma unroll
    for (int mi = 0; mi < MI; mi++) {
        #pragma unroll
        for (int ni = 0; ni < 4; ni++) {
            int n0 = ncol + ni * 8;
            if (NCHK && n0 >= Brows) continue;
            float v0 = acc[mi][ni][0], v1 = acc[mi][ni][1];
            float v2 = acc[mi][ni][2], v3 = acc[mi][ni][3];
            if (HASBIAS) {
                float b0 = bias_scale * __ldg(bias + n0);
                float b1 = bias_scale * __ldg(bias + n0 + 1);
                v0 += b0; v1 += b1; v2 += b0; v3 += b1;
            }
            if (SOFTPLUS) {
                v0 = softplus_f(v0); v1 = softplus_f(v1);
                v2 = softplus_f(v2); v3 = softplus_f(v3);
            }
            size_t r0 = (size_t)(mrow + mi * 16) * N + n0;
            size_t r1 = (size_t)(mrow + mi * 16 + 8) * N + n0;
            if (H16OUT) {
                h16* Ch = reinterpret_cast<h16*>(Cout);
                *reinterpret_cast<__half2*>(Ch + r0) =
                    __half2(__float2half_rn(v0), __float2half_rn(v1));
                *reinterpret_cast<__half2*>(Ch + r1) =
                    __half2(__float2half_rn(v2), __float2half_rn(v3));
            } else {
                float* Cf = reinterpret_cast<float*>(Cout);
                *reinterpret_cast<float2*>(Cf + r0) = make_float2(v0, v1);
                *reinterpret_cast<float2*>(Cf + r1) = make_float2(v2, v3);
            }
            if (DTSPLIT && n0 < DTRANK) {
                h16 hh, ll;
                size_t d0 = (size_t)(mrow + mi * 16) * DTRANK + n0;
                size_t d1 = (size_t)(mrow + mi * 16 + 8) * DTRANK + n0;
                split_h16(v0, hh, ll); dth[d0] = hh;     dtl[d0] = ll;
                split_h16(v1, hh, ll); dth[d0 + 1] = hh; dtl[d0 + 1] = ll;
                split_h16(v2, hh, ll); dth[d1] = hh;     dtl[d1] = ll;
                split_h16(v3, hh, ll); dth[d1 + 1] = hh; dtl[d1 + 1] = ll;
            }
        }
    }
}

// ---------------------------------------------------------------------------
// fp32 -> fp16 (round-to-nearest), contiguous
// ---------------------------------------------------------------------------
__global__ __launch_bounds__(256)
void cvt_h16_kernel(const float* __restrict__ in, h16* __restrict__ oh, int n)
{
    int i = (blockIdx.x * blockDim.x + threadIdx.x) * 4;
    if (i >= n) return;
    float4 v = *reinterpret_cast<const float4*>(in + i);
    __half2* ph = reinterpret_cast<__half2*>(oh + i);
    ph[0] = __half2(__float2half_rn(v.x), __float2half_rn(v.y));
    ph[1] = __half2(__float2half_rn(v.z), __float2half_rn(v.w));
}

// ---------------------------------------------------------------------------
// Combined weight transpose(+split) prep — ONE launch for all four weights.
//   blk ranges (32x32 tiles, 256 threads = 32x8):
//     [0,    2048): W_in  [1024,2048] -> b1h [2048,1024]          (hi only)
//     [2048, 2144): W_xdbl[1024,  96] -> bxh [  96,1024]          (hi only)
//     [2144, 2208): W_dt  [  64,1024] -> bdh/bdl [1024,64]        (hi + lo)
//     [2208, 4256): W_out [2048,1024] -> b2h [1024,2048]          (hi only)
// ---------------------------------------------------------------------------
__global__ __launch_bounds__(256)
void prep_weights_kernel(const float* __restrict__ W_in,
                         const float* __restrict__ W_xdbl,
                         const float* __restrict__ W_dt,
                         const float* __restrict__ W_out,
                         h16* __restrict__ b1h, h16* __restrict__ bxh,
                         h16* __restrict__ bdh, h16* __restrict__ bdl,
                         h16* __restrict__ b2h)
{
    __shared__ float t[32][33];
    int blk = blockIdx.x;
    const float* in;
    h16 *oh, *ol = nullptr;
    int R, C, bx, by;
    if (blk < 2048)      { in = W_in;   oh = b1h; R = 1024; C = 2048; bx = blk % 64; by = blk / 64; }
    else if (blk < 2144) { blk -= 2048; in = W_xdbl; oh = bxh; R = 1024; C = 96;   bx = blk % 3;  by = blk / 3; }
    else if (blk < 2208) { blk -= 2144; in = W_dt;  oh = bdh; ol = bdl; R = 64; C = 1024; bx = blk % 32; by = blk / 32; }
    else                 { blk -= 2208; in = W_out; oh = b2h; R = 2048; C = 1024; bx = blk % 32; by = blk / 32; }

    const int cx = bx * 32, ry = by * 32;
    const int tx = threadIdx.x & 31, ty = threadIdx.x >> 5;   // 32 x 8
    #pragma unroll
    for (int j = ty; j < 32; j += 8)
        t[j][tx] = in[(size_t)(ry + j) * C + cx + tx];
    __syncthreads();
    #pragma unroll
    for (int j = ty; j < 32; j += 8) {
        float v = t[tx][j];
        h16 h, l; split_h16(v, h, l);
        size_t o = (size_t)(cx + j) * R + ry + tx;
        oh[o] = h;
        if (ol) ol[o] = l;
    }
}

// ---------------------------------------------------------------------------
// Depthwise conv (k=4, SAME: pad left 1, right 2) + SiLU over BOTH halves,
// sliding window (4 l-outputs per thread), fp16 xz input.
//   blockIdx.y == 0: x-half -> split fp16 (xsh + xsl)
//   blockIdx.y == 1: z-half -> fp16 rn into concat right half (stride DINNER)
// ---------------------------------------------------------------------------
__global__ __launch_bounds__(256)
void conv_both_kernel(const h16* __restrict__ xz,
                      const float* __restrict__ wx, const float* __restrict__ bx,
                      const float* __restrict__ wz, const float* __restrict__ bz,
                      h16* __restrict__ xsh, h16* __restrict__ xsl,
                      h16* __restrict__ ch)
{
    const int half = blockIdx.y;
    const float* w    = half ? wz : wx;
    const float* bias = half ? bz : bx;
    const int col0 = half ? DHALF : 0;

    int idx = blockIdx.x * blockDim.x + threadIdx.x;   // < MROWS/4 * DHALF
    int c   = idx & (DHALF - 1);
    int bl4 = idx >> 10;
    int b   = bl4 >> 9;
    int l0  = (bl4 & 511) << 2;

    float w0 = w[c], w1 = w[DHALF + c], w2 = w[2 * DHALF + c], w3 = w[3 * DHALF + c];
    float bv = bias[c];

    const h16* src = xz + ((size_t)b * LSEQ) * DINNER + col0 + c;
    float win[7];
    #pragma unroll
    for (int j = 0; j < 7; j++) {
        int l = l0 + j - 1;
        win[j] = (l >= 0 && l < LSEQ) ? __half2float(src[(size_t)l * DINNER]) : 0.0f;
    }

    #pragma unroll
    for (int k = 0; k < 4; k++) {
        float acc = bv;
        acc = fmaf(win[k],     w0, acc);
        acc = fmaf(win[k + 1], w1, acc);
        acc = fmaf(win[k + 2], w2, acc);
        acc = fmaf(win[k + 3], w3, acc);
        float v = silu_f(acc);
        size_t row = (size_t)b * LSEQ + l0 + k;
        if (half == 0) {
            h16 h, lo; split_h16(v, h, lo);
            size_t o = row * DHALF + c;
            xsh[o] = h; xsl[o] = lo;
        } else {
            ch[row * DINNER + DHALF + c] = __float2half_rn(v);
        }
    }
}

// ---------------------------------------------------------------------------
// Chunk-parallel selective scan.  A[d][n] = -(n+1) => dA_n = exp(-delta)^(n+1).
//   NCHUNK=32, LCHUNK=64 -> 1024 blocks in phases 1 and 3.
//   Phase 1: per (b, chunk, dblk) compute q and S = Sum(delta).
//   Phase 2: per (b, d) sequential combine over 32 chunks -> h_start.
//   Phase 3: replay each chunk from its h_start, emit y (fp16).
// u is read hi-only (fp16 rn) — y is fp16-rounded at output anyway.
// ---------------------------------------------------------------------------
#define PW16(p1, pw)                                                    \
    float p2 = (p1) * (p1), p3 = p2 * (p1), p4 = p2 * p2;               \
    float p5 = p4 * (p1), p6 = p4 * p2, p7 = p4 * p3, p8 = p4 * p4;     \
    float pw[16] = {(p1), p2, p3, p4, p5, p6, p7, p8,                   \
                    p8 * (p1), p8 * p2, p8 * p3, p8 * p4,               \
                    p8 * p5, p8 * p6, p8 * p7, p8 * p8};

__global__ __launch_bounds__(128)
void scan_p1(const float* __restrict__ delta,
             const h16* __restrict__ uh,
             const float* __restrict__ xdbl,
             float* __restrict__ q, float* __restrict__ S)
{
    const int tid = threadIdx.x;
    const int chunk = blockIdx.x, dblk = blockIdx.y, b = blockIdx.z;
    const int d = (dblk << 7) + tid;

    __shared__ float sB[16][DSTATE];
    __shared__ float sd[16][128];
    __shared__ float su[16][128];

    float h[DSTATE];
    #pragma unroll
    for (int n = 0; n < DSTATE; n++) h[n] = 0.0f;
    float sum = 0.0f;
    const size_t baseRow = (size_t)b * LSEQ + (size_t)chunk * LCHUNK;

    for (int t0 = 0; t0 < LCHUNK; t0 += 16) {
        {
            int s = tid >> 3;
            int i = (tid & 7) << 1;
            float2 v = *reinterpret_cast<const float2*>(
                xdbl + (baseRow + t0 + s) * XDBL_N + DTRANK + i);
            sB[s][i] = v.x; sB[s][i + 1] = v.y;
        }
        #pragma unroll
        for (int s = 0; s < 16; s++) {
            size_t r = (baseRow + t0 + s) * DHALF + d;
            sd[s][tid] = delta[r];
            su[s][tid] = __half2float(uh[r]);
        }
        __syncthreads();

        #pragma unroll
        for (int s = 0; s < 16; s++) {
            float dl = sd[s][tid];
            float du = dl * su[s][tid];
            sum += dl;
            float p1 = __expf(-dl);
            PW16(p1, pw)
            #pragma unroll
            for (int n = 0; n < DSTATE; n++)
                h[n] = fmaf(pw[n], h[n], du * sB[s][n]);
        }
        __syncthreads();
    }
    const size_t cbase = ((size_t)(b * NCHUNK + chunk) * DSTATE) * DHALF + d;
    #pragma unroll
    for (int n = 0; n < DSTATE; n++) q[cbase + (size_t)n * DHALF] = h[n];
    S[(size_t)(b * NCHUNK + chunk) * DHALF + d] = sum;
}

__global__ __launch_bounds__(128)
void scan_p2(const float* __restrict__ q, const float* __restrict__ S,
             float* __restrict__ hs)
{
    const int idx = blockIdx.x * 128 + threadIdx.x;   // < 4096
    const int b = idx >> 10, d = idx & (DHALF - 1);
    float h[DSTATE];
    #pragma unroll
    for (int n = 0; n < DSTATE; n++) h[n] = 0.0f;
    for (int c = 0; c < NCHUNK; c++) {
        const size_t cbase = ((size_t)(b * NCHUNK + c) * DSTATE) * DHALF + d;
        #pragma unroll
        for (int n = 0; n < DSTATE; n++) hs[cbase + (size_t)n * DHALF] = h[n];
        float s = S[(size_t)(b * NCHUNK + c) * DHALF + d];
        float p1 = __expf(-s);
        PW16(p1, pw)
        #pragma unroll
        for (int n = 0; n < DSTATE; n++)
            h[n] = fmaf(pw[n], h[n], q[cbase + (size_t)n * DHALF]);
    }
}

__global__ __launch_bounds__(128)
void scan_p3(const float* __restrict__ delta,
             const h16* __restrict__ uh,
             const float* __restrict__ xdbl, const float* __restrict__ hs,
             const float* __restrict__ Dv,
             h16* __restrict__ cat_h)
{
    const int tid = threadIdx.x;
    const int chunk = blockIdx.x, dblk = blockIdx.y, b = blockIdx.z;
    const int d = (dblk << 7) + tid;

    __shared__ float sB[16][DSTATE];
    __shared__ float sC[16][DSTATE];
    __shared__ float sd[16][128];
    __shared__ float su[16][128];

    float h[DSTATE];
    const size_t cbase = ((size_t)(b * NCHUNK + chunk) * DSTATE) * DHALF + d;
    #pragma unroll
    for (int n = 0; n < DSTATE; n++) h[n] = hs[cbase + (size_t)n * DHALF];
    const float Dd = Dv[d];
    const size_t baseRow = (size_t)b * LSEQ + (size_t)chunk * LCHUNK;

    for (int t0 = 0; t0 < LCHUNK; t0 += 16) {
        {
            int s = tid >> 3;
            int i = (tid & 7) << 2;
            float4 v = *reinterpret_cast<const float4*>(
                xdbl + (baseRow + t0 + s) * XDBL_N + DTRANK + i);
            float vv[4] = {v.x, v.y, v.z, v.w};
            #pragma unroll
            for (int qq = 0; qq < 4; qq++) {
                int ii = i + qq;
                if (ii < DSTATE) sB[s][ii] = vv[qq];
                else             sC[s][ii - DSTATE] = vv[qq];
            }
        }
        #pragma unroll
        for (int s = 0; s < 16; s++) {
            size_t r = (baseRow + t0 + s) * DHALF + d;
            sd[s][tid] = delta[r];
            su[s][tid] = __half2float(uh[r]);
        }
        __syncthreads();

        #pragma unroll
        for (int s = 0; s < 16; s++) {
            float dl = sd[s][tid];
            float uu = su[s][tid];
            float du = dl * uu;
            float p1 = __expf(-dl);
            PW16(p1, pw)
            float y0 = 0.f, y1 = 0.f, y2 = 0.f, y3 = 0.f;
            #pragma unroll
            for (int n = 0; n < DSTATE; n += 4) {
                h[n + 0] = fmaf(pw[n + 0], h[n + 0], du * sB[s][n + 0]);
                h[n + 1] = fmaf(pw[n + 1], h[n + 1], du * sB[s][n + 1]);
                h[n + 2] = fmaf(pw[n + 2], h[n + 2], du * sB[s][n + 2]);
                h[n + 3] = fmaf(pw[n + 3], h[n + 3], du * sB[s][n + 3]);
                y0 = fmaf(h[n + 0], sC[s][n + 0], y0);
                y1 = fmaf(h[n + 1], sC[s][n + 1], y1);
                y2 = fmaf(h[n + 2], sC[s][n + 2], y2);
                y3 = fmaf(h[n + 3], sC[s][n + 3], y3);
            }
            float yv = fmaf(uu, Dd, (y0 + y1) + (y2 + y3));
            cat_h[(baseRow + t0 + s) * DINNER + d] = __float2half_rn(yv);
        }
        __syncthreads();
    }
}

// ---------------------------------------------------------------------------
// Launch
// ---------------------------------------------------------------------------
extern "C" void kernel_launch(void* const* d_in, const int* in_sizes, int n_in,
                              void* d_out, int out_size)
{
    const float* x        = (const float*)d_in[0];
    const float* W_in     = (const float*)d_in[1];
    const float* conv_x_w = (const float*)d_in[2];
    const float* conv_x_b = (const float*)d_in[3];
    const float* conv_z_w = (const float*)d_in[4];
    const float* conv_z_b = (const float*)d_in[5];
    const float* W_xdbl   = (const float*)d_in[6];
    const float* W_dt     = (const float*)d_in[7];
    const float* inv_dt   = (const float*)d_in[8];
    const float* Dvec     = (const float*)d_in[9];
    const float* W_out    = (const float*)d_in[10];
    const float* b_out    = (const float*)d_in[11];
    float* out            = (float*)d_out;

    float *p_xdbl, *p_delta, *p_q, *p_hs, *p_S;
    h16 *p_xzh, *p_a1h, *p_b1h, *p_xsh, *p_xsl, *p_bxh;
    h16 *p_dth, *p_dtl, *p_bdh, *p_bdl, *p_ch, *p_b2h;
    cudaGetSymbolAddress((void**)&p_xzh,   g_xzh);
    cudaGetSymbolAddress((void**)&p_xdbl,  g_xdbl);
    cudaGetSymbolAddress((void**)&p_delta, g_delta);
    cudaGetSymbolAddress((void**)&p_q,  g_q);
    cudaGetSymbolAddress((void**)&p_hs, g_hs);
    cudaGetSymbolAddress((void**)&p_S,  g_S);
    cudaGetSymbolAddress((void**)&p_a1h, g_a1h);
    cudaGetSymbolAddress((void**)&p_b1h, g_b1h);
    cudaGetSymbolAddress((void**)&p_xsh, g_xsh); cudaGetSymbolAddress((void**)&p_xsl, g_xsl);
    cudaGetSymbolAddress((void**)&p_bxh, g_bxh);
    cudaGetSymbolAddress((void**)&p_dth, g_dth); cudaGetSymbolAddress((void**)&p_dtl, g_dtl);
    cudaGetSymbolAddress((void**)&p_bdh, g_bdh); cudaGetSymbolAddress((void**)&p_bdl, g_bdl);
    cudaGetSymbolAddress((void**)&p_ch,  g_ch);
    cudaGetSymbolAddress((void**)&p_b2h, g_b2h);

    constexpr int SMEM_128 = 3 * (128 * 128 + 128 * 128) + 1024;   // 99328
    constexpr int SMEM_64  = 3 * (64 * 128 + 128 * 128) + 1024;    // 74752
    cudaFuncSetAttribute((const void*)gemm_mma<128,1,false,false,false,false,true>,
                         cudaFuncAttributeMaxDynamicSharedMemorySize, SMEM_128);
    cudaFuncSetAttribute((const void*)gemm_mma<128,1,false,true,false,false,false>,
                         cudaFuncAttributeMaxDynamicSharedMemorySize, SMEM_128);
    cudaFuncSetAttribute((const void*)gemm_mma<128,3,true,true,false,false,false>,
                         cudaFuncAttributeMaxDynamicSharedMemorySize, SMEM_128);
    cudaFuncSetAttribute((const void*)gemm_mma<64,2,false,false,true,true,false>,
                         cudaFuncAttributeMaxDynamicSharedMemorySize, SMEM_64);

    // 1) all weight transposes/splits in ONE launch (4256 tiles)
    prep_weights_kernel<<<4256, 256>>>(W_in, W_xdbl, W_dt, W_out,
                                       p_b1h, p_bxh, p_bdh, p_bdl, p_b2h);

    // 2) x -> fp16 (rn)
    cvt_h16_kernel<<<(MROWS * DMODEL / 4) / 256, 256>>>(x, p_a1h, MROWS * DMODEL);

    // 3) xz = x @ W_in                              [8192,2048]  (1-stream, fp16 out)
    gemm_mma<128,1,false,false,false,false,true><<<dim3(DINNER / 128, MROWS / 128), 256, SMEM_128>>>(
        p_a1h, nullptr, p_b1h, nullptr, nullptr, 0.0f, p_xzh, DINNER, DMODEL, DINNER,
        nullptr, nullptr);

    // 4) both depthwise convs + silu in one launch (fp16 xz input)
    conv_both_kernel<<<dim3((MROWS / 4 * DHALF) / 256, 2), 256>>>(
        p_xzh, conv_x_w, conv_x_b, conv_z_w, conv_z_b, p_xsh, p_xsl, p_ch);

    // 5) x_dbl = xs @ W_xdbl  [8192,96] (2-stream: (xs_hi+xs_lo) @ W_hi)
    gemm_mma<64,2,false,false,true,true,false><<<dim3(1, MROWS / 64), 256, SMEM_64>>>(
        p_xsh, p_xsl, p_bxh, nullptr, nullptr, 0.0f, p_xdbl, XDBL_N, DHALF, XDBL_N,
        p_dth, p_dtl);

    // 6) delta = softplus(dt_low @ W_dt + 2*inv_dt) [8192,1024] (3-stream)
    gemm_mma<128,3,true,true,false,false,false><<<dim3(DHALF / 128, MROWS / 128), 256, SMEM_128>>>(
        p_dth, p_dtl, p_bdh, p_bdl, inv_dt, 2.0f, p_delta, DHALF, DTRANK, DHALF,
        nullptr, nullptr);

    // 7) chunk-parallel selective scan (32 chunks) -> concat left half (fp16 rn)
    scan_p1<<<dim3(NCHUNK, 8, B_SZ), 128>>>(p_delta, p_xsh, p_xdbl, p_q, p_S);
    scan_p2<<<32, 128>>>(p_q, p_S, p_hs);
    scan_p3<<<dim3(NCHUNK, 8, B_SZ), 128>>>(p_delta, p_xsh, p_xdbl, p_hs, Dvec, p_ch);

    // 8) out = [y|z] @ W_out + b_out                [8192,1024]  (1-stream)
    gemm_mma<128,1,false,true,false,false,false><<<dim3(DMODEL / 128, MROWS / 128), 256, SMEM_128>>>(
        p_ch, nullptr, p_b2h, nullptr, b_out, 1.0f, out, DMODEL, DINNER, DMODEL,
        nullptr, nullptr);
}

// round 12
// speedup vs baseline: 1.6452x; 1.0121x over previous
#include <cuda_runtime.h>
#include <cuda_fp16.h>
#include <cstdint>
#include <cstddef>

// ---------------------------------------------------------------------------
// Problem constants (MambaVisionMixer, B=4, L=2048)
// ---------------------------------------------------------------------------
#define B_SZ    4
#define LSEQ    2048
#define DMODEL  1024
#define DINNER  2048
#define DHALF   1024
#define DSTATE  16
#define DTRANK  64
#define XDBL_N  96
#define MROWS   (B_SZ*LSEQ)   // 8192
#define NCHUNK  32
#define LCHUNK  (LSEQ/NCHUNK) // 64

typedef __half h16;

// ---------------------------------------------------------------------------
// Device scratch (static __device__ arrays — no allocations)
// ---------------------------------------------------------------------------
__device__ h16   g_xzh [(size_t)MROWS * DINNER];    // xz fp16  (32 MB)
__device__ float g_xdbl [(size_t)MROWS * XDBL_N];   // 3 MB
__device__ float g_delta[(size_t)MROWS * DHALF];    // 32 MB

__device__ float g_q [(size_t)B_SZ * NCHUNK * DSTATE * DHALF];  // 8 MB
__device__ float g_hs[(size_t)B_SZ * NCHUNK * DSTATE * DHALF];  // 8 MB
__device__ float g_S [(size_t)B_SZ * NCHUNK * DHALF];           // 512 KB

__device__ h16 g_a1h[(size_t)MROWS * DMODEL];      // x (fp16 rn)
__device__ h16 g_b1h[(size_t)DINNER * DMODEL];     // W_in^T  [2048,1024]
__device__ h16 g_xsh[(size_t)MROWS * DHALF];       // xs hi
__device__ h16 g_xsl[(size_t)MROWS * DHALF];       // xs lo (xdbl path only)
__device__ h16 g_bxh[(size_t)XDBL_N * DHALF];      // W_xdbl^T [96,1024]
__device__ h16 g_dth[(size_t)MROWS * DTRANK];      // dt_low hi [8192,64]
__device__ h16 g_dtl[(size_t)MROWS * DTRANK];
__device__ h16 g_bdh[(size_t)DHALF * DTRANK];      // W_dt^T [1024,64]
__device__ h16 g_bdl[(size_t)DHALF * DTRANK];
__device__ h16 g_ch [(size_t)MROWS * DINNER];      // [y|z] (fp16 rn) [8192,2048]
__device__ h16 g_b2h[(size_t)DMODEL * DINNER];     // W_out^T [1024,2048]

// ---------------------------------------------------------------------------
// Helpers (sm_80-era ISA only: compiles at compute_103 non-'a' target)
// ---------------------------------------------------------------------------
__device__ __forceinline__ uint32_t smem_u32(const void* p) {
    uint32_t r;
    asm("{ .reg .u64 t; cvta.to.shared.u64 t, %1; cvt.u32.u64 %0, t; }"
        : "=r"(r) : "l"(p));
    return r;
}

#define CP16(dst, src) \
    asm volatile("cp.async.cg.shared.global [%0], [%1], 16;" \
        :: "r"(dst), "l"(src) : "memory")
#define CP16Z(dst, src, sz) \
    asm volatile("cp.async.cg.shared.global [%0], [%1], 16, %2;" \
        :: "r"(dst), "l"(src), "r"(sz) : "memory")
#define CP_COMMIT() asm volatile("cp.async.commit_group;" ::: "memory")
#define CP_WAIT2()  asm volatile("cp.async.wait_group 2;" ::: "memory")

__device__ __forceinline__ void ldsm4(uint32_t* r, uint32_t addr) {
    asm volatile("ldmatrix.sync.aligned.m8n8.x4.shared.b16 {%0,%1,%2,%3}, [%4];"
        : "=r"(r[0]), "=r"(r[1]), "=r"(r[2]), "=r"(r[3]) : "r"(addr));
}

__device__ __forceinline__ void mma16816(float* d, const uint32_t* a,
                                         const uint32_t* b) {
    asm volatile(
        "mma.sync.aligned.m16n8k16.row.col.f32.f16.f16.f32 "
        "{%0,%1,%2,%3}, {%4,%5,%6,%7}, {%8,%9}, {%0,%1,%2,%3};"
        : "+f"(d[0]), "+f"(d[1]), "+f"(d[2]), "+f"(d[3])
        : "r"(a[0]), "r"(a[1]), "r"(a[2]), "r"(a[3]), "r"(b[0]), "r"(b[1]));
}

__device__ __forceinline__ float softplus_f(float x) {
    return fmaxf(x, 0.0f) + log1pf(expf(-fabsf(x)));
}
__device__ __forceinline__ float silu_f(float x) {
    return x / (1.0f + expf(-x));
}
__device__ __forceinline__ void split_h16(float v, h16& h, h16& l) {
    h = __float2half_rn(v);
    l = __float2half_rn(v - __half2float(h));
}

// ---------------------------------------------------------------------------
// Tensor-core GEMM (mma.sync fp16, fp32 accum), extended-K streams.
//   C[M,N] = A[M,K] @ B^T   (B stored [N,K] row-major)
//   NSTREAM==1: (Ahi,Bhi)
//   NSTREAM==2: (Ahi,Bhi), (Alo,Bhi)
//   NSTREAM==3: (Ahi,Bhi), (Ahi,Blo), (Alo,Bhi)
//   CTA BMx128, 8 warps (2x4), warp tile (BM/2)x32, BK=64,
//   3-stage cp.async pipeline.  H16OUT: write C as fp16 rn.
//   DTSPLIT: additionally write fp16 hi/lo of cols [0,64) to dth/dtl.
// ---------------------------------------------------------------------------
template <int BM, int NSTREAM, bool SOFTPLUS, bool HASBIAS, bool NCHK,
          bool DTSPLIT, bool H16OUT>
__global__ __launch_bounds__(256, 2)
void gemm_mma(const h16* __restrict__ Ahi, const h16* __restrict__ Alo,
              const h16* __restrict__ Bhi, const h16* __restrict__ Blo,
              const float* __restrict__ bias, float bias_scale,
              void* __restrict__ Cout, int N, int K, int Brows,
              h16* __restrict__ dth, h16* __restrict__ dtl)
{
    constexpr int MI     = BM / 32;
    constexpr int ABYTES = BM * 128;
    constexpr int STAGE  = ABYTES + 128 * 128;
    extern __shared__ char dsm[];
    const uint32_t base = (smem_u32(dsm) + 1023u) & ~1023u;

    const int tid    = threadIdx.x;
    const int rowBlk = blockIdx.y * BM;
    const int colBlk = blockIdx.x * 128;
    const int wid    = tid >> 5;
    const int lane   = tid & 31;
    const int warp_m = wid >> 2;
    const int warp_n = wid & 3;
    const int mat    = lane >> 3;
    const int rin    = lane & 7;

    const int KC     = K / 64;
    const int CHUNKS = NSTREAM * KC;

    uint32_t offA[MI][4], offB[2][4];
    #pragma unroll
    for (int mi = 0; mi < MI; mi++)
        #pragma unroll
        for (int j = 0; j < 4; j++) {
            int row = warp_m * (BM / 2) + mi * 16 + (mat & 1) * 8 + rin;
            int c   = 2 * j + (mat >> 1);
            offA[mi][j] = row * 128 + ((c ^ (row & 7)) << 4);
        }
    #pragma unroll
    for (int bi = 0; bi < 2; bi++)
        #pragma unroll
        for (int j = 0; j < 4; j++) {
            int row = warp_n * 32 + bi * 16 + (mat >> 1) * 8 + rin;
            int c   = 2 * j + (mat & 1);
            offB[bi][j] = ABYTES + row * 128 + ((c ^ (row & 7)) << 4);
        }

    float acc[MI][4][4];
    #pragma unroll
    for (int i = 0; i < MI; i++)
        #pragma unroll
        for (int j = 0; j < 4; j++)
            #pragma unroll
            for (int q = 0; q < 4; q++) acc[i][j][q] = 0.0f;

    auto load_stage = [&](int s, int c) {
        int stream;
        if (NSTREAM == 1)      stream = 0;
        else if (NSTREAM == 2) stream = (c >= KC) ? 1 : 0;
        else                   stream = (c >= 2 * KC) ? 2 : ((c >= KC) ? 1 : 0);
        int k0 = (c - stream * KC) * 64;
        const h16* Ap = Ahi;
        const h16* Bp = Bhi;
        if (NSTREAM == 2) {
            if (stream == 1) Ap = Alo;
        } else if (NSTREAM == 3) {
            if (stream == 2) Ap = Alo;
            else if (stream == 1) Bp = Blo;
        }
        uint32_t as_ = base + s * STAGE;
        uint32_t bs_ = as_ + ABYTES;
        #pragma unroll
        for (int t = 0; t < BM / 32; t++) {
            int idx = tid + t * 256;
            int r = idx >> 3, cc = idx & 7;
            uint32_t dst = as_ + r * 128 + ((cc ^ (r & 7)) << 4);
            const char* src =
                (const char*)(Ap + (size_t)(rowBlk + r) * K + k0) + cc * 16;
            CP16(dst, src);
        }
        #pragma unroll
        for (int t = 0; t < 4; t++) {
            int idx = tid + t * 256;
            int r = idx >> 3, cc = idx & 7;
            uint32_t dst = bs_ + r * 128 + ((cc ^ (r & 7)) << 4);
            if (NCHK) {
                int br = colBlk + r;
                int ok = (br < Brows);
                const char* src =
                    (const char*)(Bp + (size_t)(ok ? br : 0) * K + k0) + cc * 16;
                CP16Z(dst, src, ok ? 16u : 0u);
            } else {
                const char* src =
                    (const char*)(Bp + (size_t)(colBlk + r) * K + k0) + cc * 16;
                CP16(dst, src);
            }
        }
    };

    #pragma unroll
    for (int s = 0; s < 3; s++) { load_stage(s, s); CP_COMMIT(); }

    int slot = 0;
    #pragma unroll 1
    for (int i = 0; i < CHUNKS; i++) {
        CP_WAIT2();
        __syncthreads();
        const uint32_t sb = base + slot * STAGE;
        #pragma unroll
        for (int j = 0; j < 4; j++) {
            uint32_t Af[MI][4];
            #pragma unroll
            for (int mi = 0; mi < MI; mi++) ldsm4(Af[mi], sb + offA[mi][j]);
            uint32_t Bf[4][2];
            #pragma unroll
            for (int bi = 0; bi < 2; bi++) {
                uint32_t r[4];
                ldsm4(r, sb + offB[bi][j]);
                Bf[bi * 2 + 0][0] = r[0]; Bf[bi * 2 + 0][1] = r[1];
                Bf[bi * 2 + 1][0] = r[2]; Bf[bi * 2 + 1][1] = r[3];
            }
            #pragma unroll
            for (int mi = 0; mi < MI; mi++)
                #pragma unroll
                for (int ni = 0; ni < 4; ni++)
                    mma16816(acc[mi][ni], Af[mi], Bf[ni]);
        }
        __syncthreads();
        if (i + 3 < CHUNKS) load_stage(slot, i + 3);
        CP_COMMIT();
        slot = (slot == 2) ? 0 : slot + 1;
    }

    // epilogue
    const int mrow = rowBlk + warp_m * (BM / 2) + (lane >> 2);
    const int ncol = colBlk + warp_n * 32 + (lane & 3) * 2;
    #pragma unroll
    for (int mi = 0; mi < MI; mi++) {
        #pragma unroll
        for (int ni = 0; ni < 4; ni++) {
            int n0 = ncol + ni * 8;
            if (NCHK && n0 >= Brows) continue;
            float v0 = acc[mi][ni][0], v1 = acc[mi][ni][1];
            float v2 = acc[mi][ni][2], v3 = acc[mi][ni][3];
            if (HASBIAS) {
                float b0 = bias_scale * __ldg(bias + n0);
                float b1 = bias_scale * __ldg(bias + n0 + 1);
                v0 += b0; v1 += b1; v2 += b0; v3 += b1;
            }
            if (SOFTPLUS) {
                v0 = softplus_f(v0); v1 = softplus_f(v1);
                v2 = softplus_f(v2); v3 = softplus_f(v3);
            }
            size_t r0 = (size_t)(mrow + mi * 16) * N + n0;
            size_t r1 = (size_t)(mrow + mi * 16 + 8) * N + n0;
            if (H16OUT) {
                h16* Ch = reinterpret_cast<h16*>(Cout);
                *reinterpret_cast<__half2*>(Ch + r0) =
                    __half2(__float2half_rn(v0), __float2half_rn(v1));
                *reinterpret_cast<__half2*>(Ch + r1) =
                    __half2(__float2half_rn(v2), __float2half_rn(v3));
            } else {
                float* Cf = reinterpret_cast<float*>(Cout);
                *reinterpret_cast<float2*>(Cf + r0) = make_float2(v0, v1);
                *reinterpret_cast<float2*>(Cf + r1) = make_float2(v2, v3);
            }
            if (DTSPLIT && n0 < DTRANK) {
                h16 hh, ll;
                size_t d0 = (size_t)(mrow + mi * 16) * DTRANK + n0;
                size_t d1 = (size_t)(mrow + mi * 16 + 8) * DTRANK + n0;
                split_h16(v0, hh, ll); dth[d0] = hh;     dtl[d0] = ll;
                split_h16(v1, hh, ll); dth[d0 + 1] = hh; dtl[d0 + 1] = ll;
                split_h16(v2, hh, ll); dth[d1] = hh;     dtl[d1] = ll;
                split_h16(v3, hh, ll); dth[d1 + 1] = hh; dtl[d1 + 1] = ll;
            }
        }
    }
}

// ---------------------------------------------------------------------------
// Combined prep — ONE launch: 4 weight transposes(+split) AND x -> fp16.
//   blk ranges:
//     [0,    2048): W_in  [1024,2048] -> b1h [2048,1024]          (hi only)
//     [2048, 2144): W_xdbl[1024,  96] -> bxh [  96,1024]          (hi only)
//     [2144, 2208): W_dt  [  64,1024] -> bdh/bdl [1024,64]        (hi + lo)
//     [2208, 4256): W_out [2048,1024] -> b2h [1024,2048]          (hi only)
//     [4256,12448): x (8M floats) -> a1h fp16 rn (1024 elems/blk)
// ---------------------------------------------------------------------------
__global__ __launch_bounds__(256)
void prep_kernel(const float* __restrict__ W_in,
                 const float* __restrict__ W_xdbl,
                 const float* __restrict__ W_dt,
                 const float* __restrict__ W_out,
                 const float* __restrict__ x,
                 h16* __restrict__ b1h, h16* __restrict__ bxh,
                 h16* __restrict__ bdh, h16* __restrict__ bdl,
                 h16* __restrict__ b2h, h16* __restrict__ a1h)
{
    int blk = blockIdx.x;
    if (blk >= 4256) {
        int i = (blk - 4256) * 1024 + threadIdx.x * 4;
        float4 v = *reinterpret_cast<const float4*>(x + i);
        __half2* ph = reinterpret_cast<__half2*>(a1h + i);
        ph[0] = __half2(__float2half_rn(v.x), __float2half_rn(v.y));
        ph[1] = __half2(__float2half_rn(v.z), __float2half_rn(v.w));
        return;
    }

    __shared__ float t[32][33];
    const float* in;
    h16 *oh, *ol = nullptr;
    int R, C, bx, by;
    if (blk < 2048)      { in = W_in;   oh = b1h; R = 1024; C = 2048; bx = blk % 64; by = blk / 64; }
    else if (blk < 2144) { blk -= 2048; in = W_xdbl; oh = bxh; R = 1024; C = 96;   bx = blk % 3;  by = blk / 3; }
    else if (blk < 2208) { blk -= 2144; in = W_dt;  oh = bdh; ol = bdl; R = 64; C = 1024; bx = blk % 32; by = blk / 32; }
    else                 { blk -= 2208; in = W_out; oh = b2h; R = 2048; C = 1024; bx = blk % 32; by = blk / 32; }

    const int cx = bx * 32, ry = by * 32;
    const int tx = threadIdx.x & 31, ty = threadIdx.x >> 5;   // 32 x 8
    #pragma unroll
    for (int j = ty; j < 32; j += 8)
        t[j][tx] = in[(size_t)(ry + j) * C + cx + tx];
    __syncthreads();
    #pragma unroll
    for (int j = ty; j < 32; j += 8) {
        float v = t[tx][j];
        h16 h, l; split_h16(v, h, l);
        size_t o = (size_t)(cx + j) * R + ry + tx;
        oh[o] = h;
        if (ol) ol[o] = l;
    }
}

// ---------------------------------------------------------------------------
// Depthwise conv (k=4, SAME: pad left 1, right 2) + SiLU over BOTH halves,
// half2-vectorized: each thread handles 2 channels x 4 consecutive l outputs.
//   blockIdx.y == 0: x-half -> split fp16 (xsh + xsl)
//   blockIdx.y == 1: z-half -> fp16 rn into concat right half (stride DINNER)
// ---------------------------------------------------------------------------
__global__ __launch_bounds__(256)
void conv_both_kernel(const h16* __restrict__ xz,
                      const float* __restrict__ wx, const float* __restrict__ bx,
                      const float* __restrict__ wz, const float* __restrict__ bz,
                      h16* __restrict__ xsh, h16* __restrict__ xsl,
                      h16* __restrict__ ch)
{
    const int half = blockIdx.y;
    const float* w    = half ? wz : wx;
    const float* bias = half ? bz : bx;
    const int col0 = half ? DHALF : 0;

    int idx = blockIdx.x * blockDim.x + threadIdx.x;   // < MROWS/4 * DHALF/2
    int c2  = (idx & 511) << 1;          // channel pair base
    int bl4 = idx >> 9;
    int b   = bl4 >> 9;
    int l0  = (bl4 & 511) << 2;

    float2 w0 = *reinterpret_cast<const float2*>(w + c2);
    float2 w1 = *reinterpret_cast<const float2*>(w + DHALF + c2);
    float2 w2 = *reinterpret_cast<const float2*>(w + 2 * DHALF + c2);
    float2 w3 = *reinterpret_cast<const float2*>(w + 3 * DHALF + c2);
    float2 bv = *reinterpret_cast<const float2*>(bias + c2);

    const __half2* src = reinterpret_cast<const __half2*>(
        xz + (size_t)b * LSEQ * DINNER + col0 + c2);
    float2 win[7];
    #pragma unroll
    for (int j = 0; j < 7; j++) {
        int l = l0 + j - 1;
        win[j] = (l >= 0 && l < LSEQ)
                 ? __half22float2(src[(size_t)l * (DINNER / 2)])
                 : make_float2(0.0f, 0.0f);
    }

    #pragma unroll
    for (int k = 0; k < 4; k++) {
        float ax = bv.x, ay = bv.y;
        ax = fmaf(win[k].x,     w0.x, ax); ay = fmaf(win[k].y,     w0.y, ay);
        ax = fmaf(win[k + 1].x, w1.x, ax); ay = fmaf(win[k + 1].y, w1.y, ay);
        ax = fmaf(win[k + 2].x, w2.x, ax); ay = fmaf(win[k + 2].y, w2.y, ay);
        ax = fmaf(win[k + 3].x, w3.x, ax); ay = fmaf(win[k + 3].y, w3.y, ay);
        float vx = silu_f(ax), vy = silu_f(ay);
        size_t row = (size_t)b * LSEQ + l0 + k;
        if (half == 0) {
            h16 hx, lx, hy, ly;
            split_h16(vx, hx, lx); split_h16(vy, hy, ly);
            size_t o = row * DHALF + c2;
            *reinterpret_cast<__half2*>(xsh + o) = __half2(hx, hy);
            *reinterpret_cast<__half2*>(xsl + o) = __half2(lx, ly);
        } else {
            *reinterpret_cast<__half2*>(ch + row * DINNER + DHALF + c2) =
                __half2(__float2half_rn(vx), __float2half_rn(vy));
        }
    }
}

// ---------------------------------------------------------------------------
// Chunk-parallel selective scan.  A[d][n] = -(n+1) => dA_n = exp(-delta)^(n+1).
//   NCHUNK=32, LCHUNK=64 -> 1024 blocks in phases 1 and 3.
// u is read hi-only (fp16 rn).
// ---------------------------------------------------------------------------
#define PW16(p1, pw)                                                    \
    float p2 = (p1) * (p1), p3 = p2 * (p1), p4 = p2 * p2;               \
    float p5 = p4 * (p1), p6 = p4 * p2, p7 = p4 * p3, p8 = p4 * p4;     \
    float pw[16] = {(p1), p2, p3, p4, p5, p6, p7, p8,                   \
                    p8 * (p1), p8 * p2, p8 * p3, p8 * p4,               \
                    p8 * p5, p8 * p6, p8 * p7, p8 * p8};

__global__ __launch_bounds__(128)
void scan_p1(const float* __restrict__ delta,
             const h16* __restrict__ uh,
             const float* __restrict__ xdbl,
             float* __restrict__ q, float* __restrict__ S)
{
    const int tid = threadIdx.x;
    const int chunk = blockIdx.x, dblk = blockIdx.y, b = blockIdx.z;
    const int d = (dblk << 7) + tid;

    __shared__ float sB[16][DSTATE];
    __shared__ float sd[16][128];
    __shared__ float su[16][128];

    float h[DSTATE];
    #pragma unroll
    for (int n = 0; n < DSTATE; n++) h[n] = 0.0f;
    float sum = 0.0f;
    const size_t baseRow = (size_t)b * LSEQ + (size_t)chunk * LCHUNK;

    for (int t0 = 0; t0 < LCHUNK; t0 += 16) {
        {
            int s = tid >> 3;
            int i = (tid & 7) << 1;
            float2 v = *reinterpret_cast<const float2*>(
                xdbl + (baseRow + t0 + s) * XDBL_N + DTRANK + i);
            sB[s][i] = v.x; sB[s][i + 1] = v.y;
        }
        #pragma unroll
        for (int s = 0; s < 16; s++) {
            size_t r = (baseRow + t0 + s) * DHALF + d;
            sd[s][tid] = delta[r];
            su[s][tid] = __half2float(uh[r]);
        }
        __syncthreads();

        #pragma unroll
        for (int s = 0; s < 16; s++) {
            float dl = sd[s][tid];
            float du = dl * su[s][tid];
            sum += dl;
            float p1 = __expf(-dl);
            PW16(p1, pw)
            #pragma unroll
            for (int n = 0; n < DSTATE; n++)
                h[n] = fmaf(pw[n], h[n], du * sB[s][n]);
        }
        __syncthreads();
    }
    const size_t cbase = ((size_t)(b * NCHUNK + chunk) * DSTATE) * DHALF + d;
    #pragma unroll
    for (int n = 0; n < DSTATE; n++) q[cbase + (size_t)n * DHALF] = h[n];
    S[(size_t)(b * NCHUNK + chunk) * DHALF + d] = sum;
}

__global__ __launch_bounds__(128)
void scan_p2(const float* __restrict__ q, const float* __restrict__ S,
             float* __restrict__ hs)
{
    const int idx = blockIdx.x * 128 + threadIdx.x;   // < 4096
    const int b = idx >> 10, d = idx & (DHALF - 1);
    float h[DSTATE];
    #pragma unroll
    for (int n = 0; n < DSTATE; n++) h[n] = 0.0f;
    for (int c = 0; c < NCHUNK; c++) {
        const size_t cbase = ((size_t)(b * NCHUNK + c) * DSTATE) * DHALF + d;
        #pragma unroll
        for (int n = 0; n < DSTATE; n++) hs[cbase + (size_t)n * DHALF] = h[n];
        float s = S[(size_t)(b * NCHUNK + c) * DHALF + d];
        float p1 = __expf(-s);
        PW16(p1, pw)
        #pragma unroll
        for (int n = 0; n < DSTATE; n++)
            h[n] = fmaf(pw[n], h[n], q[cbase + (size_t)n * DHALF]);
    }
}

__global__ __launch_bounds__(128)
void scan_p3(const float* __restrict__ delta,
             const h16* __restrict__ uh,
             const float* __restrict__ xdbl, const float* __restrict__ hs,
             const float* __restrict__ Dv,
             h16* __restrict__ cat_h)
{
    const int tid = threadIdx.x;
    const int chunk = blockIdx.x, dblk = blockIdx.y, b = blockIdx.z;
    const int d = (dblk << 7) + tid;

    __shared__ float sB[16][DSTATE];
    __shared__ float sC[16][DSTATE];
    __shared__ float sd[16][128];
    __shared__ float su[16][128];

    float h[DSTATE];
    const size_t cbase = ((size_t)(b * NCHUNK + chunk) * DSTATE) * DHALF + d;
    #pragma unroll
    for (int n = 0; n < DSTATE; n++) h[n] = hs[cbase + (size_t)n * DHALF];
    const float Dd = Dv[d];
    const size_t baseRow = (size_t)b * LSEQ + (size_t)chunk * LCHUNK;

    for (int t0 = 0; t0 < LCHUNK; t0 += 16) {
        {
            int s = tid >> 3;
            int i = (tid & 7) << 2;
            float4 v = *reinterpret_cast<const float4*>(
                xdbl + (baseRow + t0 + s) * XDBL_N + DTRANK + i);
            float vv[4] = {v.x, v.y, v.z, v.w};
            #pragma unroll
            for (int qq = 0; qq < 4; qq++) {
                int ii = i + qq;
                if (ii < DSTATE) sB[s][ii] = vv[qq];
                else             sC[s][ii - DSTATE] = vv[qq];
            }
        }
        #pragma unroll
        for (int s = 0; s < 16; s++) {
            size_t r = (baseRow + t0 + s) * DHALF + d;
            sd[s][tid] = delta[r];
            su[s][tid] = __half2float(uh[r]);
        }
        __syncthreads();

        #pragma unroll
        for (int s = 0; s < 16; s++) {
            float dl = sd[s][tid];
            float uu = su[s][tid];
            float du = dl * uu;
            float p1 = __expf(-dl);
            PW16(p1, pw)
            float y0 = 0.f, y1 = 0.f, y2 = 0.f, y3 = 0.f;
            #pragma unroll
            for (int n = 0; n < DSTATE; n += 4) {
                h[n + 0] = fmaf(pw[n + 0], h[n + 0], du * sB[s][n + 0]);
                h[n + 1] = fmaf(pw[n + 1], h[n + 1], du * sB[s][n + 1]);
                h[n + 2] = fmaf(pw[n + 2], h[n + 2], du * sB[s][n + 2]);
                h[n + 3] = fmaf(pw[n + 3], h[n + 3], du * sB[s][n + 3]);
                y0 = fmaf(h[n + 0], sC[s][n + 0], y0);
                y1 = fmaf(h[n + 1], sC[s][n + 1], y1);
                y2 = fmaf(h[n + 2], sC[s][n + 2], y2);
                y3 = fmaf(h[n + 3], sC[s][n + 3], y3);
            }
            float yv = fmaf(uu, Dd, (y0 + y1) + (y2 + y3));
            cat_h[(baseRow + t0 + s) * DINNER + d] = __float2half_rn(yv);
        }
        __syncthreads();
    }
}

// ---------------------------------------------------------------------------
// Launch
// ---------------------------------------------------------------------------
extern "C" void kernel_launch(void* const* d_in, const int* in_sizes, int n_in,
                              void* d_out, int out_size)
{
    const float* x        = (const float*)d_in[0];
    const float* W_in     = (const float*)d_in[1];
    const float* conv_x_w = (const float*)d_in[2];
    const float* conv_x_b = (const float*)d_in[3];
    const float* conv_z_w = (const float*)d_in[4];
    const float* conv_z_b = (const float*)d_in[5];
    const float* W_xdbl   = (const float*)d_in[6];
    const float* W_dt     = (const float*)d_in[7];
    const float* inv_dt   = (const float*)d_in[8];
    const float* Dvec     = (const float*)d_in[9];
    const float* W_out    = (const float*)d_in[10];
    const float* b_out    = (const float*)d_in[11];
    float* out            = (float*)d_out;

    float *p_xdbl, *p_delta, *p_q, *p_hs, *p_S;
    h16 *p_xzh, *p_a1h, *p_b1h, *p_xsh, *p_xsl, *p_bxh;
    h16 *p_dth, *p_dtl, *p_bdh, *p_bdl, *p_ch, *p_b2h;
    cudaGetSymbolAddress((void**)&p_xzh,   g_xzh);
    cudaGetSymbolAddress((void**)&p_xdbl,  g_xdbl);
    cudaGetSymbolAddress((void**)&p_delta, g_delta);
    cudaGetSymbolAddress((void**)&p_q,  g_q);
    cudaGetSymbolAddress((void**)&p_hs, g_hs);
    cudaGetSymbolAddress((void**)&p_S,  g_S);
    cudaGetSymbolAddress((void**)&p_a1h, g_a1h);
    cudaGetSymbolAddress((void**)&p_b1h, g_b1h);
    cudaGetSymbolAddress((void**)&p_xsh, g_xsh); cudaGetSymbolAddress((void**)&p_xsl, g_xsl);
    cudaGetSymbolAddress((void**)&p_bxh, g_bxh);
    cudaGetSymbolAddress((void**)&p_dth, g_dth); cudaGetSymbolAddress((void**)&p_dtl, g_dtl);
    cudaGetSymbolAddress((void**)&p_bdh, g_bdh); cudaGetSymbolAddress((void**)&p_bdl, g_bdl);
    cudaGetSymbolAddress((void**)&p_ch,  g_ch);
    cudaGetSymbolAddress((void**)&p_b2h, g_b2h);

    constexpr int SMEM_128 = 3 * (128 * 128 + 128 * 128) + 1024;   // 99328
    constexpr int SMEM_64  = 3 * (64 * 128 + 128 * 128) + 1024;    // 74752
    cudaFuncSetAttribute((const void*)gemm_mma<128,1,false,false,false,false,true>,
                         cudaFuncAttributeMaxDynamicSharedMemorySize, SMEM_128);
    cudaFuncSetAttribute((const void*)gemm_mma<128,1,false,true,false,false,false>,
                         cudaFuncAttributeMaxDynamicSharedMemorySize, SMEM_128);
    cudaFuncSetAttribute((const void*)gemm_mma<128,3,true,true,false,false,false>,
                         cudaFuncAttributeMaxDynamicSharedMemorySize, SMEM_128);
    cudaFuncSetAttribute((const void*)gemm_mma<64,2,false,false,true,true,false>,
                         cudaFuncAttributeMaxDynamicSharedMemorySize, SMEM_64);

    // 1) all prep in ONE launch: 4 weight transposes/splits + x->fp16
    prep_kernel<<<4256 + 8192, 256>>>(W_in, W_xdbl, W_dt, W_out, x,
                                      p_b1h, p_bxh, p_bdh, p_bdl, p_b2h, p_a1h);

    // 2) xz = x @ W_in                              [8192,2048]  (1-stream, fp16 out)
    gemm_mma<128,1,false,false,false,false,true><<<dim3(DINNER / 128, MROWS / 128), 256, SMEM_128>>>(
        p_a1h, nullptr, p_b1h, nullptr, nullptr, 0.0f, p_xzh, DINNER, DMODEL, DINNER,
        nullptr, nullptr);

    // 3) both depthwise convs + silu (half2-vectorized, one launch)
    conv_both_kernel<<<dim3((MROWS / 4 * DHALF / 2) / 256, 2), 256>>>(
        p_xzh, conv_x_w, conv_x_b, conv_z_w, conv_z_b, p_xsh, p_xsl, p_ch);

    // 4) x_dbl = xs @ W_xdbl  [8192,96] (2-stream: (xs_hi+xs_lo) @ W_hi)
    gemm_mma<64,2,false,false,true,true,false><<<dim3(1, MROWS / 64), 256, SMEM_64>>>(
        p_xsh, p_xsl, p_bxh, nullptr, nullptr, 0.0f, p_xdbl, XDBL_N, DHALF, XDBL_N,
        p_dth, p_dtl);

    // 5) delta = softplus(dt_low @ W_dt + 2*inv_dt) [8192,1024] (3-stream)
    gemm_mma<128,3,true,true,false,false,false><<<dim3(DHALF / 128, MROWS / 128), 256, SMEM_128>>>(
        p_dth, p_dtl, p_bdh, p_bdl, inv_dt, 2.0f, p_delta, DHALF, DTRANK, DHALF,
        nullptr, nullptr);

    // 6) chunk-parallel selective scan (32 chunks) -> concat left half (fp16 rn)
    scan_p1<<<dim3(NCHUNK, 8, B_SZ), 128>>>(p_delta, p_xsh, p_xdbl, p_q, p_S);
    scan_p2<<<32, 128>>>(p_q, p_S, p_hs);
    scan_p3<<<dim3(NCHUNK, 8, B_SZ), 128>>>(p_delta, p_xsh, p_xdbl, p_hs, Dvec, p_ch);

    // 7) out = [y|z] @ W_out + b_out                [8192,1024]  (1-stream)
    gemm_mma<128,1,false,true,false,false,false><<<dim3(DMODEL / 128, MROWS / 128), 256, SMEM_128>>>(
        p_ch, nullptr, p_b2h, nullptr, b_out, 1.0f, out, DMODEL, DINNER, DMODEL,
        nullptr, nullptr);
}